// round 13
// baseline (speedup 1.0000x reference)
#include <cuda_runtime.h>
#include <math.h>

#define GH 160
#define GW 160
#define NPIX (GH*GW)
#define CCH 256
#define NA 9
#define NANCH (NPIX*NA)
#define TOPK 6000
#define NW 94
#define POSTK 300
#define GCAP 8192
#define IMG 2560.0f
#define STRIDE 16
#define DWHC ((float)4.135166556742356)
#define NMS_THR 0.7f
#define MINSZ 16.0f
#define PADW 162
#define PADA (PADW*PADW)

typedef unsigned long long u64;

// ---------- static scratch ----------
__device__ __align__(16) float  g_pad[CCH*PADA];
__device__ __align__(16) u64    g_wt[9*CCH*CCH];     // [tap][ci][co] dup (w,w)
__device__ __align__(16) float  g_feat[CCH*NPIX];
__device__ float4 g_boxes[NANCH];
__device__ float  g_scores[NANCH];
__device__ __align__(16) unsigned g_keys[NANCH];
__device__ float4 g_tb[TOPK];
__device__ float  g_tarea[TOPK];
__device__ float  g_tsc[TOPK];
__device__ u64    g_valid[NW];
__device__ u64    g_mask[(size_t)TOPK*NW];

// ---------- f32x2 helpers ----------
__device__ __forceinline__ u64 pk2(float lo, float hi) {
    u64 r; asm("mov.b64 %0, {%1, %2};" : "=l"(r) : "f"(lo), "f"(hi)); return r;
}
__device__ __forceinline__ void upk2(u64 v, float& lo, float& hi) {
    asm("mov.b64 {%0, %1}, %2;" : "=f"(lo), "=f"(hi) : "l"(v));
}
__device__ __forceinline__ void ffma2(u64& c, u64 a, u64 b) {
    asm("fma.rn.f32x2 %0, %1, %2, %0;" : "+l"(c) : "l"(a), "l"(b));
}

// ---------- prep: zero-pad ----------
__global__ void k_pad(const float* __restrict__ feat) {
    int i = blockIdx.x * 256 + threadIdx.x;
    if (i >= CCH * PADA) return;
    int ci = i / PADA, rem = i % PADA;
    int y = rem / PADW, x = rem % PADW;
    float v = 0.f;
    if (y >= 1 && y <= GH && x >= 1 && x <= GW)
        v = feat[ci * NPIX + (y - 1) * GW + (x - 1)];
    g_pad[i] = v;
}

// ---------- prep: weight transpose + dup ----------
__global__ void k_wprep(const float* __restrict__ w) {
    int i = blockIdx.x * 256 + threadIdx.x;
    if (i >= 9 * CCH * CCH) return;
    int tap = i / (CCH*CCH), r = i % (CCH*CCH);
    int ci = r >> 8, co = r & 255;
    float v = w[(size_t)co * (CCH*9) + ci * 9 + tap];
    g_wt[i] = pk2(v, v);
}

// ---------- K1: conv implicit GEMM (measured 822us) ----------
__global__ __launch_bounds__(256, 2)
void k_conv(const float* __restrict__ bias) {
    __shared__ __align__(16) u64   As[2][8][128];
    __shared__ __align__(16) float Bs[2][8][4][32];
    int tid = threadIdx.x;
    int cog = tid >> 4;
    int pxg = tid & 15;
    int rr  = pxg >> 2;
    int cc0 = (pxg & 3) * 8;
    int gqA = (((cc0 >> 2) + 0) ^ rr) << 2;
    int gqB = (((cc0 >> 2) + 1) ^ rr) << 2;
    int pt  = blockIdx.x;
    int ty  = pt / 5, tx = pt % 5;
    int y0  = ty * 4, x0 = tx * 32;
    int co0 = blockIdx.y * 128;

    int aoff0, aoff1, asto0, asto1;
    {
        int j0 = tid * 2, j1 = (tid + 256) * 2;
        aoff0 = (j0 >> 7) * 256 + co0 + (j0 & 127);
        aoff1 = (j1 >> 7) * 256 + co0 + (j1 & 127);
        asto0 = (j0 >> 7) * 128 + (j0 & 127);
        asto1 = (j1 >> 7) * 128 + (j1 & 127);
    }
    int binv[4], bsto[4];
#pragma unroll
    for (int q = 0; q < 4; q++) {
        int f = tid + q * 256;
        int k = f >> 7, r2 = (f >> 5) & 3, cc = f & 31;
        binv[q] = k * PADA + (y0 + r2) * PADW + x0 + cc;
        bsto[q] = (k * 4 + r2) * 32 + ((((cc >> 2) ^ r2) << 2) | (cc & 3));
    }

    u64 acc[8][4];
#pragma unroll
    for (int u = 0; u < 8; u++)
#pragma unroll
        for (int p = 0; p < 4; p++) acc[u][p] = 0ull;

    ulonglong2 pa[2]; float pb[4];

    auto loadCh = [&](int ch) {
        int tap = ch >> 5;
        int ky = (tap * 11) >> 5;
        int kx = tap - ky * 3;
        int offB = ((ch & 31) << 3) * PADA + ky * PADW + kx;
        const u64* ap = g_wt + (size_t)ch * 2048;
        pa[0] = *(const ulonglong2*)(ap + aoff0);
        pa[1] = *(const ulonglong2*)(ap + aoff1);
#pragma unroll
        for (int q = 0; q < 4; q++)
            pb[q] = g_pad[offB + binv[q]];
    };
    auto storeCh = [&](int buf) {
        u64* as = &As[buf][0][0];
        *(ulonglong2*)(as + asto0) = pa[0];
        *(ulonglong2*)(as + asto1) = pa[1];
        float* bp = &Bs[buf][0][0][0];
#pragma unroll
        for (int q = 0; q < 4; q++)
            bp[bsto[q]] = pb[q];
    };

    loadCh(0);
    storeCh(0);
    for (int ch = 0; ch < 288; ch++) {
        __syncthreads();
        if (ch + 1 < 288) loadCh(ch + 1);
        int buf = ch & 1;
#pragma unroll
        for (int k = 0; k < 8; k++) {
            ulonglong2 bA = *(const ulonglong2*)&Bs[buf][k][rr][gqA];
            ulonglong2 bB = *(const ulonglong2*)&Bs[buf][k][rr][gqB];
#pragma unroll
            for (int uu = 0; uu < 4; uu++) {
                ulonglong2 a = *(const ulonglong2*)&As[buf][k][cog * 8 + uu * 2];
                ffma2(acc[uu*2+0][0], bA.x, a.x);
                ffma2(acc[uu*2+0][1], bA.y, a.x);
                ffma2(acc[uu*2+0][2], bB.x, a.x);
                ffma2(acc[uu*2+0][3], bB.y, a.x);
                ffma2(acc[uu*2+1][0], bA.x, a.y);
                ffma2(acc[uu*2+1][1], bA.y, a.y);
                ffma2(acc[uu*2+1][2], bB.x, a.y);
                ffma2(acc[uu*2+1][3], bB.y, a.y);
            }
        }
        if (ch + 1 < 288) storeCh((ch + 1) & 1);
    }

#pragma unroll
    for (int u = 0; u < 8; u++) {
        int co = co0 + cog * 8 + u;
        float bb = bias[co];
        float v[8];
#pragma unroll
        for (int p = 0; p < 4; p++) upk2(acc[u][p], v[2*p], v[2*p+1]);
#pragma unroll
        for (int q = 0; q < 8; q++) v[q] = fmaxf(v[q] + bb, 0.f);
        size_t o = (size_t)co * NPIX + (y0 + rr) * GW + x0 + cc0;
        *(float4*)&g_feat[o]     = make_float4(v[0], v[1], v[2], v[3]);
        *(float4*)&g_feat[o + 4] = make_float4(v[4], v[5], v[6], v[7]);
    }
}

// ---------- K2: heads (float4 weights) + decode ----------
__global__ __launch_bounds__(128)
void k_heads(const float* __restrict__ cls_w, const float* __restrict__ cls_b,
             const float* __restrict__ bbox_w, const float* __restrict__ bbox_b) {
    __shared__ __align__(16) float ws[45][256];
    __shared__ float bs[45];
    int tid = threadIdx.x;
    for (int t = tid; t < 45*256; t += 128) {
        int j = t / 256, c = t % 256;
        ws[j][c] = (j < 9) ? cls_w[j*256 + c] : bbox_w[(j-9)*256 + c];
    }
    if (tid < 45) bs[tid] = (tid < 9) ? cls_b[tid] : bbox_b[tid - 9];
    __syncthreads();

    int pix = blockIdx.x * 128 + tid;
    float acc[45];
#pragma unroll
    for (int j = 0; j < 45; j++) acc[j] = 0.f;
    for (int c0 = 0; c0 < 256; c0 += 4) {
        float f0 = g_feat[(c0 + 0) * NPIX + pix];
        float f1 = g_feat[(c0 + 1) * NPIX + pix];
        float f2 = g_feat[(c0 + 2) * NPIX + pix];
        float f3 = g_feat[(c0 + 3) * NPIX + pix];
#pragma unroll
        for (int j = 0; j < 45; j++) {
            float4 w4 = *(const float4*)&ws[j][c0];
            float a = acc[j];
            a = fmaf(w4.x, f0, a);
            a = fmaf(w4.y, f1, a);
            a = fmaf(w4.z, f2, a);
            a = fmaf(w4.w, f3, a);
            acc[j] = a;
        }
    }
#pragma unroll
    for (int j = 0; j < 45; j++) acc[j] += bs[j];

    int y = pix / GW, x = pix % GW;
    float fx = (float)(x * STRIDE), fy = (float)(y * STRIDE);
    const float ars[3] = {0.5f, 1.0f, 2.0f};
    const float scl[3] = {128.f, 256.f, 512.f};

#pragma unroll
    for (int a = 0; a < NA; a++) {
        int ai = a / 3, si = a % 3;
        float hr = sqrtf(ars[ai]);
        float wr = __fdiv_rn(1.0f, hr);
        float wsz = __fmul_rn(wr, scl[si]);
        float hsz = __fmul_rn(hr, scl[si]);
        float bx1 = rintf(__fmul_rn(-wsz, 0.5f));
        float bx2 = rintf(__fmul_rn( wsz, 0.5f));
        float by1 = rintf(__fmul_rn(-hsz, 0.5f));
        float by2 = rintf(__fmul_rn( hsz, 0.5f));
        float ax1 = __fadd_rn(fx, bx1), ax2 = __fadd_rn(fx, bx2);
        float ay1 = __fadd_rn(fy, by1), ay2 = __fadd_rn(fy, by2);
        float aw = __fsub_rn(ax2, ax1), ah = __fsub_rn(ay2, ay1);
        float cx = __fadd_rn(ax1, __fmul_rn(0.5f, aw));
        float cy = __fadd_rn(ay1, __fmul_rn(0.5f, ah));

        float score = __fdiv_rn(1.0f, __fadd_rn(1.0f, expf(-acc[a])));

        float dx = acc[9 + a*4 + 0];
        float dy = acc[9 + a*4 + 1];
        float dw = fminf(acc[9 + a*4 + 2], DWHC);
        float dh = fminf(acc[9 + a*4 + 3], DWHC);

        float pcx = __fadd_rn(__fmul_rn(dx, aw), cx);
        float pcy = __fadd_rn(__fmul_rn(dy, ah), cy);
        float pw  = __fmul_rn(expf(dw), aw);
        float ph  = __fmul_rn(expf(dh), ah);

        float x1 = __fsub_rn(pcx, __fmul_rn(0.5f, pw));
        float x2 = __fadd_rn(pcx, __fmul_rn(0.5f, pw));
        float y1 = __fsub_rn(pcy, __fmul_rn(0.5f, ph));
        float y2 = __fadd_rn(pcy, __fmul_rn(0.5f, ph));
        x1 = fminf(fmaxf(x1, 0.f), IMG);
        x2 = fminf(fmaxf(x2, 0.f), IMG);
        y1 = fminf(fmaxf(y1, 0.f), IMG);
        y2 = fminf(fmaxf(y2, 0.f), IMG);

        int idx = pix * NA + a;
        g_boxes[idx] = make_float4(x1, y1, x2, y2);
        g_scores[idx] = score;
        unsigned b = __float_as_uint(score);
        g_keys[idx] = b ^ ((b & 0x80000000u) ? 0xFFFFFFFFu : 0x80000000u);
    }
}

// ---------- fused top-K select: 4x radix + gather + sort + post (ONE block) ----------
#define NV4 (NANCH/4)          // 57600
#define NIT 57                 // ceil(57600/1024)
__global__ __launch_bounds__(1024)
void k_select() {
    extern __shared__ u64 s[];              // GCAP u64 = 64KB; low 32KB aliased as warp hists
    __shared__ unsigned bins[256];
    __shared__ unsigned wbase[32];
    __shared__ unsigned sPref, sAbove, sCnt;
    int t = threadIdx.x;
    int wid = t >> 5, lane = t & 31;
    unsigned* whist = (unsigned*)s;          // 32 warps * 256 bins
    if (t == 0) { sPref = 0u; sAbove = 0u; }

    // ---- 4 radix passes (per-warp private hists, no atomics) ----
    for (int pass = 0; pass < 4; pass++) {
        int shift = 24 - pass * 8;
        for (int i = t; i < 32 * 256; i += 1024) whist[i] = 0u;
        __syncthreads();
        unsigned pref = sPref;
        unsigned pmask = (pass == 0) ? 0u : (0xFFFFFFFFu << (32 - 8 * pass));
        unsigned* myh = whist + wid * 256;
        for (int it = 0; it < NIT; it++) {
            int i = t + it * 1024;
            bool inb = i < NV4;
            uint4 kv = inb ? ((const uint4*)g_keys)[i] : make_uint4(0u,0u,0u,0u);
            unsigned ka[4] = {kv.x, kv.y, kv.z, kv.w};
#pragma unroll
            for (int q = 0; q < 4; q++) {
                unsigned key = ka[q];
                bool c = inb && ((key & pmask) == (pref & pmask));
                unsigned act = __ballot_sync(0xFFFFFFFFu, c);
                if (c) {
                    unsigned bin = (key >> shift) & 255u;
                    unsigned m = __match_any_sync(act, bin);
                    if (lane == (unsigned)(__ffs(m) - 1))
                        myh[bin] += __popc(m);
                }
            }
        }
        __syncthreads();
        if (t < 256) {
            unsigned sum = 0;
            for (int w = 0; w < 32; w++) sum += whist[w * 256 + t];
            bins[t] = sum;
        }
        __syncthreads();
        if (t == 0) {
            unsigned acc = sAbove;
            for (int b = 255; b >= 0; b--) {
                unsigned h = bins[b];
                if (acc < TOPK && acc + h >= TOPK) {
                    sPref |= ((unsigned)b) << shift;
                    sAbove = acc;
                    break;
                }
                acc += h;
            }
        }
        __syncthreads();
    }
    unsigned thr = sPref;

    // ---- gather: count sweep (no atomics) ----
    unsigned wtot = 0;
    for (int it = 0; it < NIT; it++) {
        int i = t + it * 1024;
        bool inb = i < NV4;
        uint4 kv = inb ? ((const uint4*)g_keys)[i] : make_uint4(0u,0u,0u,0u);
        unsigned ka[4] = {kv.x, kv.y, kv.z, kv.w};
#pragma unroll
        for (int q = 0; q < 4; q++) {
            bool win = inb && (ka[q] >= thr);
            wtot += __popc(__ballot_sync(0xFFFFFFFFu, win));
        }
    }
    if (lane == 0) wbase[wid] = wtot;
    __syncthreads();
    if (t == 0) {
        unsigned a = 0;
        for (int w = 0; w < 32; w++) { unsigned c = wbase[w]; wbase[w] = a; a += c; }
        sCnt = a;
    }
    __syncthreads();
    unsigned n = sCnt; if (n > GCAP) n = GCAP;

    // ---- gather: write sweep ----
    {
        unsigned run = wbase[wid];
        for (int it = 0; it < NIT; it++) {
            int i = t + it * 1024;
            bool inb = i < NV4;
            uint4 kv = inb ? ((const uint4*)g_keys)[i] : make_uint4(0u,0u,0u,0u);
            unsigned ka[4] = {kv.x, kv.y, kv.z, kv.w};
#pragma unroll
            for (int q = 0; q < 4; q++) {
                unsigned key = ka[q];
                bool win = inb && (key >= thr);
                unsigned m = __ballot_sync(0xFFFFFFFFu, win);
                if (win) {
                    unsigned pos = run + __popc(m & ((1u << lane) - 1u));
                    if (pos < GCAP) {
                        unsigned idx = (unsigned)(i * 4 + q);
                        s[pos] = ((u64)key << 32) | (unsigned)(~idx);
                    }
                }
                run += __popc(m);
            }
        }
    }
    // pad [n, GCAP)
    for (int i = t; i < GCAP; i += 1024) if (i >= (int)n) s[i] = 0ull;
    __syncthreads();

    // ---- bitonic sort (descending) ----
    for (int k = 2; k <= GCAP; k <<= 1) {
        for (int j = k >> 1; j > 0; j >>= 1) {
            int ls = __ffs(j) - 1;
            for (int p = t; p < GCAP/2; p += 1024) {
                int i = ((p >> ls) << (ls + 1)) | (p & (j - 1));
                int x = i + j;
                u64 a = s[i], b = s[x];
                bool desc = ((i & k) == 0);
                if ((a < b) == desc) { s[i] = b; s[x] = a; }
            }
            __syncthreads();
        }
    }

    // ---- post: unpack top-6000, compute areas + valid bits ----
    for (int w = t; w < NW; w += 1024) g_valid[w] = 0ull;
    __syncthreads();
    for (int i = t; i < TOPK; i += 1024) {
        u64 kk = s[i];
        unsigned idx = ~(unsigned)(kk & 0xFFFFFFFFull);
        float4 b = g_boxes[idx];
        g_tb[i] = b;
        float bw = __fsub_rn(b.z, b.x), bh = __fsub_rn(b.w, b.y);
        g_tarea[i] = __fmul_rn(bw, bh);
        g_tsc[i] = g_scores[idx];
        if (bw >= MINSZ && bh >= MINSZ)
            atomicOr(&g_valid[i >> 6], 1ull << (i & 63));
    }
}

// ---------- NMS mask (r8-measured form) ----------
__global__ void k_mask() {
    int bi = blockIdx.y, bj = blockIdx.x;
    __shared__ float4 cb[64];
    __shared__ float  ca[64];
    int jb = bj * 64;
    int nc = min(64, TOPK - jb);
    int t = threadIdx.x;
    if (t < nc) { cb[t] = g_tb[jb + t]; ca[t] = g_tarea[jb + t]; }
    __syncthreads();
    int i = bi * 64 + t;
    if (i >= TOPK) return;
    u64 w = 0ull;
    if (bj >= bi) {
        float4 b = g_tb[i];
        float ai = g_tarea[i];
        for (int c = 0; c < nc; c++) {
            int j = jb + c;
            if (j <= i) continue;
            float4 o = cb[c];
            float xl = fmaxf(b.x, o.x), yt = fmaxf(b.y, o.y);
            float xr = fminf(b.z, o.z), yb = fminf(b.w, o.w);
            float iw = fmaxf(__fsub_rn(xr, xl), 0.f);
            float ih = fmaxf(__fsub_rn(yb, yt), 0.f);
            float inter = __fmul_rn(iw, ih);
            float iou = __fdiv_rn(inter, __fsub_rn(__fadd_rn(ai, ca[c]), inter));
            if (iou > NMS_THR) w |= 1ull << c;
        }
    }
    g_mask[(size_t)i * NW + bj] = w;
}

// ---------- NMS reduce + emit (fused) ----------
__global__ void k_reduce_out(float* __restrict__ out) {
    extern __shared__ u64 dynsm[];          // 2 * 64 * NW u64
    __shared__ u64 remv[NW];
    __shared__ u64 curKept;
    int t = threadIdx.x;                    // 256
    u64* buf0 = dynsm;
    u64* buf1 = dynsm + 64 * NW;
    if (t < NW) remv[t] = 0ull;
    for (int idx = t; idx < 64 * NW; idx += 256) {
        int r = idx / NW, wd = idx - r * NW;
        buf0[idx] = g_mask[(size_t)r * NW + wd];
    }
    __syncthreads();
    for (int cw = 0; cw < NW; cw++) {
        u64* cur = (cw & 1) ? buf1 : buf0;
        u64* nxt = (cw & 1) ? buf0 : buf1;
        int base = cw * 64;
        int nr = min(64, TOPK - base);
        if (t >= 96 && cw + 1 < NW) {
            int base2 = (cw + 1) * 64;
            int nr2 = min(64, TOPK - base2);
            int wd = cw + 1 + (t - 96);
            if (wd < NW) {
                const u64* src = g_mask + (size_t)base2 * NW + wd;
#pragma unroll 4
                for (int r = 0; r < nr2; r++)
                    nxt[r * NW + wd] = src[(size_t)r * NW];
            }
        }
        if (t == 0) {
            u64 span = (nr == 64) ? ~0ull : ((1ull << nr) - 1ull);
            u64 rem = remv[cw] | ~g_valid[cw];
            u64 live = ~rem & span;
            while (live) {
                int b = __ffsll(live) - 1;
                rem |= cur[b * NW + cw];
                live &= live - 1;
                live &= ~rem;
            }
            remv[cw] = rem;
            curKept = ~rem & span;
        }
        __syncthreads();
        u64 kept = curKept;
        if (t > cw && t < NW) {
            u64 a = remv[t], kk = kept;
            while (kk) {
                int b = __ffsll(kk) - 1;
                kk &= kk - 1;
                a |= cur[b * NW + t];
            }
            remv[t] = a;
        }
        __syncthreads();
    }
    // ---- emit top-300 ----
    __shared__ u64 keep[NW];
    __shared__ int ks[NW], ns[NW];
    __shared__ int Kc;
    if (t < NW) {
        u64 k = ~remv[t];
        if (t == NW - 1) k &= (1ull << 48) - 1ull;
        keep[t] = k;
    }
    __syncthreads();
    if (t == 0) {
        int a = 0, b = 0;
        for (int w = 0; w < NW; w++) {
            ks[w] = a; ns[w] = b;
            int nb = (w == NW - 1) ? 48 : 64;
            int p = __popcll(keep[w]);
            a += p; b += nb - p;
        }
        Kc = min(a, POSTK);
    }
    __syncthreads();
    int kc = Kc;
    for (int i = t; i < TOPK; i += 256) {
        int w = i >> 6, b = i & 63;
        u64 kw = keep[w];
        u64 low = (b == 0) ? 0ull : (kw & ((1ull << b) - 1ull));
        bool isk = (kw >> b) & 1ull;
        if (isk) {
            int pos = ks[w] + __popcll(low);
            if (pos < POSTK) {
                float4 bb = g_tb[i];
                out[pos*5+0] = bb.x; out[pos*5+1] = bb.y;
                out[pos*5+2] = bb.z; out[pos*5+3] = bb.w;
                out[pos*5+4] = g_tsc[i];
            }
        } else {
            u64 nlow = (b == 0) ? 0ull : ((~kw) & ((1ull << b) - 1ull));
            int pos = kc + ns[w] + __popcll(nlow);
            if (pos < POSTK) {
                float4 bb = g_tb[i];
                out[pos*5+0] = bb.x; out[pos*5+1] = bb.y;
                out[pos*5+2] = bb.z; out[pos*5+3] = bb.w;
                out[pos*5+4] = -1.0f;
            }
        }
    }
}

extern "C" void kernel_launch(void* const* d_in, const int* in_sizes, int n_in,
                              void* d_out, int out_size) {
    const float* feat   = (const float*)d_in[0];
    const float* conv_w = (const float*)d_in[2];
    const float* conv_b = (const float*)d_in[3];
    const float* cls_w  = (const float*)d_in[4];
    const float* cls_b  = (const float*)d_in[5];
    const float* bbox_w = (const float*)d_in[6];
    const float* bbox_b = (const float*)d_in[7];
    float* out = (float*)d_out;

    cudaFuncSetAttribute(k_select, cudaFuncAttributeMaxDynamicSharedMemorySize,
                         GCAP * sizeof(u64));
    cudaFuncSetAttribute(k_reduce_out, cudaFuncAttributeMaxDynamicSharedMemorySize,
                         2 * 64 * NW * sizeof(u64));

    k_pad<<<(CCH*PADA + 255) / 256, 256>>>(feat);
    k_wprep<<<(9*CCH*CCH + 255) / 256, 256>>>(conv_w);
    k_conv<<<dim3(200, 2), 256>>>(conv_b);
    k_heads<<<200, 128>>>(cls_w, cls_b, bbox_w, bbox_b);
    k_select<<<1, 1024, GCAP * sizeof(u64)>>>();
    k_mask<<<dim3(94, 94), 64>>>();
    k_reduce_out<<<1, 256, 2 * 64 * NW * sizeof(u64)>>>(out);
}

// round 14
// speedup vs baseline: 1.0901x; 1.0901x over previous
#include <cuda_runtime.h>
#include <math.h>

#define GH 160
#define GW 160
#define NPIX (GH*GW)
#define CCH 256
#define NA 9
#define NANCH (NPIX*NA)
#define TOPK 6000
#define NW 94
#define POSTK 300
#define GCAP 8192
#define IMG 2560.0f
#define STRIDE 16
#define DWHC ((float)4.135166556742356)
#define NMS_THR 0.7f
#define MINSZ 16.0f
#define PADW 162
#define PADA (PADW*PADW)

typedef unsigned long long u64;

// ---------- static scratch ----------
__device__ __align__(16) float  g_pad[CCH*PADA];
__device__ __align__(16) u64    g_wt[9*CCH*CCH];     // [tap][ci][co] dup (w,w)
__device__ __align__(16) float  g_feat[CCH*NPIX];
__device__ float4 g_boxes[NANCH];
__device__ float  g_scores[NANCH];
__device__ __align__(16) unsigned g_keys[NANCH];
__device__ unsigned g_h256[256];
__device__ unsigned g_pref, g_above2, g_thr, g_gcnt;
__device__ u64    g_gath[GCAP];
__device__ float4 g_tb[TOPK];
__device__ float  g_tarea[TOPK];
__device__ float  g_tsc[TOPK];
__device__ u64    g_valid[NW];
__device__ u64    g_mask[(size_t)TOPK*NW];
__device__ u64    g_remv[NW];

// ---------- helpers ----------
__device__ __forceinline__ u64 pk2(float lo, float hi) {
    u64 r; asm("mov.b64 %0, {%1, %2};" : "=l"(r) : "f"(lo), "f"(hi)); return r;
}
__device__ __forceinline__ void upk2(u64 v, float& lo, float& hi) {
    asm("mov.b64 {%0, %1}, %2;" : "=f"(lo), "=f"(hi) : "l"(v));
}
__device__ __forceinline__ void ffma2(u64& c, u64 a, u64 b) {
    asm("fma.rn.f32x2 %0, %1, %2, %0;" : "+l"(c) : "l"(a), "l"(b));
}
__device__ __forceinline__ unsigned sm2u(const void* p) {
    unsigned r;
    asm("{ .reg .u64 t; cvta.to.shared.u64 t, %1; cvt.u32.u64 %0, t; }"
        : "=r"(r) : "l"(p));
    return r;
}
#define CPA16(s, g) asm volatile("cp.async.cg.shared.global [%0], [%1], 16;" :: "r"(s), "l"(g))
#define CPA4(s, g)  asm volatile("cp.async.ca.shared.global [%0], [%1], 4;"  :: "r"(s), "l"(g))
#define CPCOMMIT()  asm volatile("cp.async.commit_group;" ::: "memory")
#define CPWAIT0()   asm volatile("cp.async.wait_group 0;" ::: "memory")

// ---------- K0: clear ----------
__global__ void k_clear() {
    int i = threadIdx.x;
    if (i < 256) g_h256[i] = 0u;
    if (i < NW) g_valid[i] = 0ull;
    if (i == 0) { g_gcnt = 0u; g_pref = 0u; g_above2 = 0u; }
}

// ---------- prep: zero-pad ----------
__global__ void k_pad(const float* __restrict__ feat) {
    int i = blockIdx.x * 256 + threadIdx.x;
    if (i >= CCH * PADA) return;
    int ci = i / PADA, rem = i % PADA;
    int y = rem / PADW, x = rem % PADW;
    float v = 0.f;
    if (y >= 1 && y <= GH && x >= 1 && x <= GW)
        v = feat[ci * NPIX + (y - 1) * GW + (x - 1)];
    g_pad[i] = v;
}

// ---------- prep: weight transpose + dup ----------
__global__ void k_wprep(const float* __restrict__ w) {
    int i = blockIdx.x * 256 + threadIdx.x;
    if (i >= 9 * CCH * CCH) return;
    int tap = i / (CCH*CCH), r = i % (CCH*CCH);
    int ci = r >> 8, co = r & 255;
    float v = w[(size_t)co * (CCH*9) + ci * 9 + tap];
    g_wt[i] = pk2(v, v);
}

// ---------- K1: conv implicit GEMM + cp.async staging ----------
__global__ __launch_bounds__(256, 2)
void k_conv(const float* __restrict__ bias) {
    __shared__ __align__(16) u64   As[2][8][128];
    __shared__ __align__(16) float Bs[2][8][4][32];
    int tid = threadIdx.x;
    int cog = tid >> 4;
    int pxg = tid & 15;
    int rr  = pxg >> 2;
    int cc0 = (pxg & 3) * 8;
    int gqA = (((cc0 >> 2) + 0) ^ rr) << 2;
    int gqB = (((cc0 >> 2) + 1) ^ rr) << 2;
    int pt  = blockIdx.x;
    int ty  = pt / 5, tx = pt % 5;
    int y0  = ty * 4, x0 = tx * 32;
    int co0 = blockIdx.y * 128;

    // thread-constant components
    int aoff0, aoff1, asto0, asto1;
    {
        int j0 = tid * 2, j1 = (tid + 256) * 2;
        aoff0 = (j0 >> 7) * 256 + co0 + (j0 & 127);
        aoff1 = (j1 >> 7) * 256 + co0 + (j1 & 127);
        asto0 = (j0 >> 7) * 128 + (j0 & 127);
        asto1 = (j1 >> 7) * 128 + (j1 & 127);
    }
    int binv[4], bsto[4];
#pragma unroll
    for (int q = 0; q < 4; q++) {
        int f = tid + q * 256;
        int k = f >> 7, r2 = (f >> 5) & 3, cc = f & 31;
        binv[q] = k * PADA + (y0 + r2) * PADW + x0 + cc;
        bsto[q] = (k * 4 + r2) * 32 + ((((cc >> 2) ^ r2) << 2) | (cc & 3));
    }
    unsigned baseA = sm2u(&As[0][0][0]);
    unsigned baseB = sm2u(&Bs[0][0][0][0]);
    unsigned dA0 = baseA + asto0 * 8, dA1 = baseA + asto1 * 8;
    unsigned dB0 = baseB + bsto[0] * 4, dB1 = baseB + bsto[1] * 4;
    unsigned dB2 = baseB + bsto[2] * 4, dB3 = baseB + bsto[3] * 4;

    u64 acc[8][4];
#pragma unroll
    for (int u = 0; u < 8; u++)
#pragma unroll
        for (int p = 0; p < 4; p++) acc[u][p] = 0ull;

    auto issueCh = [&](int ch, int buf) {
        int tap = ch >> 5;
        int ky = (tap * 11) >> 5;
        int kx = tap - ky * 3;
        int offB = ((ch & 31) << 3) * PADA + ky * PADW + kx;
        const char* apb = (const char*)g_wt + (size_t)ch * 16384;
        unsigned oa = buf * 8192;       // A buffer stride bytes
        unsigned ob = buf * 4096;       // B buffer stride bytes
        CPA16(dA0 + oa, apb + (size_t)aoff0 * 8);
        CPA16(dA1 + oa, apb + (size_t)aoff1 * 8);
        const float* bp = g_pad + offB;
        CPA4(dB0 + ob, bp + binv[0]);
        CPA4(dB1 + ob, bp + binv[1]);
        CPA4(dB2 + ob, bp + binv[2]);
        CPA4(dB3 + ob, bp + binv[3]);
        CPCOMMIT();
    };

    issueCh(0, 0);
    CPWAIT0();
    __syncthreads();
    for (int ch = 0; ch < 288; ch++) {
        if (ch + 1 < 288) issueCh(ch + 1, (ch + 1) & 1);
        int buf = ch & 1;
#pragma unroll
        for (int k = 0; k < 8; k++) {
            ulonglong2 bA = *(const ulonglong2*)&Bs[buf][k][rr][gqA];
            ulonglong2 bB = *(const ulonglong2*)&Bs[buf][k][rr][gqB];
#pragma unroll
            for (int uu = 0; uu < 4; uu++) {
                ulonglong2 a = *(const ulonglong2*)&As[buf][k][cog * 8 + uu * 2];
                ffma2(acc[uu*2+0][0], bA.x, a.x);
                ffma2(acc[uu*2+0][1], bA.y, a.x);
                ffma2(acc[uu*2+0][2], bB.x, a.x);
                ffma2(acc[uu*2+0][3], bB.y, a.x);
                ffma2(acc[uu*2+1][0], bA.x, a.y);
                ffma2(acc[uu*2+1][1], bA.y, a.y);
                ffma2(acc[uu*2+1][2], bB.x, a.y);
                ffma2(acc[uu*2+1][3], bB.y, a.y);
            }
        }
        if (ch + 1 < 288) CPWAIT0();
        __syncthreads();
    }

#pragma unroll
    for (int u = 0; u < 8; u++) {
        int co = co0 + cog * 8 + u;
        float bb = bias[co];
        float v[8];
#pragma unroll
        for (int p = 0; p < 4; p++) upk2(acc[u][p], v[2*p], v[2*p+1]);
#pragma unroll
        for (int q = 0; q < 8; q++) v[q] = fmaxf(v[q] + bb, 0.f);
        size_t o = (size_t)co * NPIX + (y0 + rr) * GW + x0 + cc0;
        *(float4*)&g_feat[o]     = make_float4(v[0], v[1], v[2], v[3]);
        *(float4*)&g_feat[o + 4] = make_float4(v[4], v[5], v[6], v[7]);
    }
}

// ---------- K2: heads (float4 weights) + decode ----------
__global__ __launch_bounds__(128)
void k_heads(const float* __restrict__ cls_w, const float* __restrict__ cls_b,
             const float* __restrict__ bbox_w, const float* __restrict__ bbox_b) {
    __shared__ __align__(16) float ws[45][256];
    __shared__ float bs[45];
    int tid = threadIdx.x;
    for (int t = tid; t < 45*256; t += 128) {
        int j = t / 256, c = t % 256;
        ws[j][c] = (j < 9) ? cls_w[j*256 + c] : bbox_w[(j-9)*256 + c];
    }
    if (tid < 45) bs[tid] = (tid < 9) ? cls_b[tid] : bbox_b[tid - 9];
    __syncthreads();

    int pix = blockIdx.x * 128 + tid;
    float acc[45];
#pragma unroll
    for (int j = 0; j < 45; j++) acc[j] = 0.f;
    for (int c0 = 0; c0 < 256; c0 += 4) {
        float f0 = g_feat[(c0 + 0) * NPIX + pix];
        float f1 = g_feat[(c0 + 1) * NPIX + pix];
        float f2 = g_feat[(c0 + 2) * NPIX + pix];
        float f3 = g_feat[(c0 + 3) * NPIX + pix];
#pragma unroll
        for (int j = 0; j < 45; j++) {
            float4 w4 = *(const float4*)&ws[j][c0];
            float a = acc[j];
            a = fmaf(w4.x, f0, a);
            a = fmaf(w4.y, f1, a);
            a = fmaf(w4.z, f2, a);
            a = fmaf(w4.w, f3, a);
            acc[j] = a;
        }
    }
#pragma unroll
    for (int j = 0; j < 45; j++) acc[j] += bs[j];

    int y = pix / GW, x = pix % GW;
    float fx = (float)(x * STRIDE), fy = (float)(y * STRIDE);
    const float ars[3] = {0.5f, 1.0f, 2.0f};
    const float scl[3] = {128.f, 256.f, 512.f};

#pragma unroll
    for (int a = 0; a < NA; a++) {
        int ai = a / 3, si = a % 3;
        float hr = sqrtf(ars[ai]);
        float wr = __fdiv_rn(1.0f, hr);
        float wsz = __fmul_rn(wr, scl[si]);
        float hsz = __fmul_rn(hr, scl[si]);
        float bx1 = rintf(__fmul_rn(-wsz, 0.5f));
        float bx2 = rintf(__fmul_rn( wsz, 0.5f));
        float by1 = rintf(__fmul_rn(-hsz, 0.5f));
        float by2 = rintf(__fmul_rn( hsz, 0.5f));
        float ax1 = __fadd_rn(fx, bx1), ax2 = __fadd_rn(fx, bx2);
        float ay1 = __fadd_rn(fy, by1), ay2 = __fadd_rn(fy, by2);
        float aw = __fsub_rn(ax2, ax1), ah = __fsub_rn(ay2, ay1);
        float cx = __fadd_rn(ax1, __fmul_rn(0.5f, aw));
        float cy = __fadd_rn(ay1, __fmul_rn(0.5f, ah));

        float score = __fdiv_rn(1.0f, __fadd_rn(1.0f, expf(-acc[a])));

        float dx = acc[9 + a*4 + 0];
        float dy = acc[9 + a*4 + 1];
        float dw = fminf(acc[9 + a*4 + 2], DWHC);
        float dh = fminf(acc[9 + a*4 + 3], DWHC);

        float pcx = __fadd_rn(__fmul_rn(dx, aw), cx);
        float pcy = __fadd_rn(__fmul_rn(dy, ah), cy);
        float pw  = __fmul_rn(expf(dw), aw);
        float ph  = __fmul_rn(expf(dh), ah);

        float x1 = __fsub_rn(pcx, __fmul_rn(0.5f, pw));
        float x2 = __fadd_rn(pcx, __fmul_rn(0.5f, pw));
        float y1 = __fsub_rn(pcy, __fmul_rn(0.5f, ph));
        float y2 = __fadd_rn(pcy, __fmul_rn(0.5f, ph));
        x1 = fminf(fmaxf(x1, 0.f), IMG);
        x2 = fminf(fmaxf(x2, 0.f), IMG);
        y1 = fminf(fmaxf(y1, 0.f), IMG);
        y2 = fminf(fmaxf(y2, 0.f), IMG);

        int idx = pix * NA + a;
        g_boxes[idx] = make_float4(x1, y1, x2, y2);
        g_scores[idx] = score;
        unsigned b = __float_as_uint(score);
        g_keys[idx] = b ^ ((b & 0x80000000u) ? 0xFFFFFFFFu : 0x80000000u);
    }
}

// ---------- radix select: 8-bit digit passes ----------
__global__ void k_hist8(int shift, unsigned pmask) {
    __shared__ unsigned sh[256];
    int t = threadIdx.x;
    for (int i = t; i < 256; i += 1024) sh[i] = 0;
    __syncthreads();
    int i = blockIdx.x * 1024 + t;
    unsigned key = g_keys[i];
    unsigned pref = g_pref;
    bool c = ((key & pmask) == (pref & pmask));
    unsigned act = __ballot_sync(0xFFFFFFFFu, c);
    if (c) {
        unsigned bin = (key >> shift) & 255u;
        unsigned m = __match_any_sync(act, bin);
        if ((t & 31) == (unsigned)(__ffs(m) - 1))
            atomicAdd(&sh[bin], __popc(m));
    }
    __syncthreads();
    for (int b = t; b < 256; b += 1024)
        if (sh[b]) atomicAdd(&g_h256[b], sh[b]);
}

__global__ void k_scan8(int shift, int last) {
    __shared__ unsigned bins[256];
    int t = threadIdx.x;
    bins[t] = g_h256[t];
    g_h256[t] = 0;
    __syncthreads();
    if (t == 0) {
        unsigned acc = g_above2;
        for (int b = 255; b >= 0; b--) {
            unsigned h = bins[b];
            if (acc < TOPK && acc + h >= TOPK) {
                g_pref |= ((unsigned)b) << shift;
                g_above2 = acc;
                if (last) g_thr = g_pref;
                break;
            }
            acc += h;
        }
    }
}

__global__ void k_gather() {
    __shared__ unsigned wcnt[32], wbase[32], bbase;
    int i = blockIdx.x * 1024 + threadIdx.x;
    unsigned key = g_keys[i];
    bool win = key >= g_thr;
    unsigned b = __ballot_sync(0xFFFFFFFFu, win);
    unsigned lane = threadIdx.x & 31, wid = threadIdx.x >> 5;
    if (lane == 0) wcnt[wid] = __popc(b);
    __syncthreads();
    if (threadIdx.x == 0) {
        unsigned tot = 0;
        for (int w = 0; w < 32; w++) { wbase[w] = tot; tot += wcnt[w]; }
        bbase = atomicAdd(&g_gcnt, tot);
    }
    __syncthreads();
    if (win) {
        unsigned pos = bbase + wbase[wid] + __popc(b & ((1u << lane) - 1u));
        if (pos < GCAP)
            g_gath[pos] = ((u64)key << 32) | (unsigned)(~i);
    }
}

// ---------- bitonic sort in shared memory ----------
__global__ void k_sort() {
    extern __shared__ u64 s[];
    int t = threadIdx.x;
    unsigned n = g_gcnt; if (n > GCAP) n = GCAP;
    for (int i = t; i < GCAP; i += 1024)
        s[i] = (i < (int)n) ? g_gath[i] : 0ull;
    __syncthreads();
    for (int k = 2; k <= GCAP; k <<= 1) {
        for (int j = k >> 1; j > 0; j >>= 1) {
            int ls = __ffs(j) - 1;
            for (int p = t; p < GCAP/2; p += 1024) {
                int i = ((p >> ls) << (ls + 1)) | (p & (j - 1));
                int x = i + j;
                u64 a = s[i], b = s[x];
                bool desc = ((i & k) == 0);
                if ((a < b) == desc) { s[i] = b; s[x] = a; }
            }
            __syncthreads();
        }
    }
    for (int i = t; i < TOPK; i += 1024) g_gath[i] = s[i];
}

// ---------- unpack top-6000 ----------
__global__ void k_post() {
    int i = blockIdx.x * 128 + threadIdx.x;
    if (i >= TOPK) return;
    u64 kk = g_gath[i];
    unsigned idx = ~(unsigned)(kk & 0xFFFFFFFFull);
    float4 b = g_boxes[idx];
    g_tb[i] = b;
    float bw = __fsub_rn(b.z, b.x), bh = __fsub_rn(b.w, b.y);
    g_tarea[i] = __fmul_rn(bw, bh);
    g_tsc[i] = g_scores[idx];
    if (bw >= MINSZ && bh >= MINSZ)
        atomicOr(&g_valid[i >> 6], 1ull << (i & 63));
}

// ---------- NMS mask ----------
__global__ void k_mask() {
    int bi = blockIdx.y, bj = blockIdx.x;
    __shared__ float4 cb[64];
    __shared__ float  ca[64];
    int jb = bj * 64;
    int nc = min(64, TOPK - jb);
    int t = threadIdx.x;
    if (t < nc) { cb[t] = g_tb[jb + t]; ca[t] = g_tarea[jb + t]; }
    __syncthreads();
    int i = bi * 64 + t;
    if (i >= TOPK) return;
    u64 w = 0ull;
    if (bj >= bi) {
        float4 b = g_tb[i];
        float ai = g_tarea[i];
        for (int c = 0; c < nc; c++) {
            int j = jb + c;
            if (j <= i) continue;
            float4 o = cb[c];
            float xl = fmaxf(b.x, o.x), yt = fmaxf(b.y, o.y);
            float xr = fminf(b.z, o.z), yb = fminf(b.w, o.w);
            float iw = fmaxf(__fsub_rn(xr, xl), 0.f);
            float ih = fmaxf(__fsub_rn(yb, yt), 0.f);
            float inter = __fmul_rn(iw, ih);
            float iou = __fdiv_rn(inter, __fsub_rn(__fadd_rn(ai, ca[c]), inter));
            if (iou > NMS_THR) w |= 1ull << c;
        }
    }
    g_mask[(size_t)i * NW + bj] = w;
}

// ---------- NMS reduce (r12 form) ----------
__global__ void k_reduce() {
    extern __shared__ u64 dynsm[];
    __shared__ u64 remv[NW];
    __shared__ u64 curKept;
    int t = threadIdx.x;
    u64* buf0 = dynsm;
    u64* buf1 = dynsm + 64 * NW;
    if (t < NW) remv[t] = 0ull;
    for (int idx = t; idx < 64 * NW; idx += 256) {
        int r = idx / NW, wd = idx - r * NW;
        buf0[idx] = g_mask[(size_t)r * NW + wd];
    }
    __syncthreads();
    for (int cw = 0; cw < NW; cw++) {
        u64* cur = (cw & 1) ? buf1 : buf0;
        u64* nxt = (cw & 1) ? buf0 : buf1;
        int base = cw * 64;
        int nr = min(64, TOPK - base);
        if (t >= 96 && cw + 1 < NW) {
            int base2 = (cw + 1) * 64;
            int nr2 = min(64, TOPK - base2);
            int wd = cw + 1 + (t - 96);
            if (wd < NW) {
                const u64* src = g_mask + (size_t)base2 * NW + wd;
#pragma unroll 4
                for (int r = 0; r < nr2; r++)
                    nxt[r * NW + wd] = src[(size_t)r * NW];
            }
        }
        if (t == 0) {
            u64 span = (nr == 64) ? ~0ull : ((1ull << nr) - 1ull);
            u64 rem = remv[cw] | ~g_valid[cw];
            u64 live = ~rem & span;
            while (live) {
                int b = __ffsll(live) - 1;
                rem |= cur[b * NW + cw];
                live &= live - 1;
                live &= ~rem;
            }
            remv[cw] = rem;
            curKept = ~rem & span;
        }
        __syncthreads();
        u64 kept = curKept;
        if (t > cw && t < NW) {
            u64 a = remv[t], kk = kept;
            while (kk) {
                int b = __ffsll(kk) - 1;
                kk &= kk - 1;
                a |= cur[b * NW + t];
            }
            remv[t] = a;
        }
        __syncthreads();
    }
    if (t < NW) g_remv[t] = remv[t];
}

// ---------- emit top-300 ----------
__global__ void k_out(float* __restrict__ out) {
    __shared__ u64 keep[NW];
    __shared__ int ks[NW], ns[NW];
    __shared__ int Kc;
    int t = threadIdx.x;
    if (t < NW) {
        u64 k = ~g_remv[t];
        if (t == NW - 1) k &= (1ull << 48) - 1ull;
        keep[t] = k;
    }
    __syncthreads();
    if (t == 0) {
        int a = 0, b = 0;
        for (int w = 0; w < NW; w++) {
            ks[w] = a; ns[w] = b;
            int nb = (w == NW - 1) ? 48 : 64;
            int p = __popcll(keep[w]);
            a += p; b += nb - p;
        }
        Kc = min(a, POSTK);
    }
    __syncthreads();
    int kc = Kc;
    for (int i = t; i < TOPK; i += 128) {
        int w = i >> 6, b = i & 63;
        u64 kw = keep[w];
        u64 low = (b == 0) ? 0ull : (kw & ((1ull << b) - 1ull));
        bool isk = (kw >> b) & 1ull;
        if (isk) {
            int pos = ks[w] + __popcll(low);
            if (pos < POSTK) {
                float4 bb = g_tb[i];
                out[pos*5+0] = bb.x; out[pos*5+1] = bb.y;
                out[pos*5+2] = bb.z; out[pos*5+3] = bb.w;
                out[pos*5+4] = g_tsc[i];
            }
        } else {
            u64 nlow = (b == 0) ? 0ull : ((~kw) & ((1ull << b) - 1ull));
            int pos = kc + ns[w] + __popcll(nlow);
            if (pos < POSTK) {
                float4 bb = g_tb[i];
                out[pos*5+0] = bb.x; out[pos*5+1] = bb.y;
                out[pos*5+2] = bb.z; out[pos*5+3] = bb.w;
                out[pos*5+4] = -1.0f;
            }
        }
    }
}

extern "C" void kernel_launch(void* const* d_in, const int* in_sizes, int n_in,
                              void* d_out, int out_size) {
    const float* feat   = (const float*)d_in[0];
    const float* conv_w = (const float*)d_in[2];
    const float* conv_b = (const float*)d_in[3];
    const float* cls_w  = (const float*)d_in[4];
    const float* cls_b  = (const float*)d_in[5];
    const float* bbox_w = (const float*)d_in[6];
    const float* bbox_b = (const float*)d_in[7];
    float* out = (float*)d_out;

    cudaFuncSetAttribute(k_sort, cudaFuncAttributeMaxDynamicSharedMemorySize,
                         GCAP * sizeof(u64));
    cudaFuncSetAttribute(k_reduce, cudaFuncAttributeMaxDynamicSharedMemorySize,
                         2 * 64 * NW * sizeof(u64));

    k_clear<<<1, 256>>>();
    k_pad<<<(CCH*PADA + 255) / 256, 256>>>(feat);
    k_wprep<<<(9*CCH*CCH + 255) / 256, 256>>>(conv_w);
    k_conv<<<dim3(200, 2), 256>>>(conv_b);
    k_heads<<<200, 128>>>(cls_w, cls_b, bbox_w, bbox_b);
    k_hist8<<<225, 1024>>>(24, 0x00000000u);
    k_scan8<<<1, 256>>>(24, 0);
    k_hist8<<<225, 1024>>>(16, 0xFF000000u);
    k_scan8<<<1, 256>>>(16, 0);
    k_hist8<<<225, 1024>>>(8,  0xFFFF0000u);
    k_scan8<<<1, 256>>>(8, 0);
    k_hist8<<<225, 1024>>>(0,  0xFFFFFF00u);
    k_scan8<<<1, 256>>>(0, 1);
    k_gather<<<225, 1024>>>();
    k_sort<<<1, 1024, GCAP * sizeof(u64)>>>();
    k_post<<<47, 128>>>();
    k_mask<<<dim3(94, 94), 64>>>();
    k_reduce<<<1, 256, 2 * 64 * NW * sizeof(u64)>>>();
    k_out<<<1, 128>>>(out);
}

// round 15
// speedup vs baseline: 1.0943x; 1.0039x over previous
#include <cuda_runtime.h>
#include <math.h>

#define GH 160
#define GW 160
#define NPIX (GH*GW)
#define CCH 256
#define NA 9
#define NANCH (NPIX*NA)
#define TOPK 6000
#define NW 94
#define POSTK 300
#define GCAP 8192
#define IMG 2560.0f
#define STRIDE 16
#define DWHC ((float)4.135166556742356)
#define NMS_THR 0.7f
#define MINSZ 16.0f
#define PADW 162
#define PADA (PADW*PADW)

typedef unsigned long long u64;

// ---------- static scratch ----------
__device__ __align__(16) float  g_pad[CCH*PADA];
__device__ __align__(16) u64    g_wt[9*CCH*CCH];     // [tap][ci][co] dup (w,w)
__device__ __align__(16) float  g_feat[CCH*NPIX];
__device__ float4 g_boxes[NANCH];
__device__ float  g_scores[NANCH];
__device__ __align__(16) unsigned g_keys[NANCH];
__device__ unsigned g_h256[256];
__device__ unsigned g_pref, g_above2, g_thr, g_gcnt;
__device__ u64    g_gath[GCAP];
__device__ float4 g_tb[TOPK];
__device__ float  g_tarea[TOPK];
__device__ float  g_tsc[TOPK];
__device__ u64    g_valid[NW];
__device__ u64    g_mask[(size_t)TOPK*NW];
__device__ u64    g_remv[NW];

// ---------- helpers ----------
__device__ __forceinline__ u64 pk2(float lo, float hi) {
    u64 r; asm("mov.b64 %0, {%1, %2};" : "=l"(r) : "f"(lo), "f"(hi)); return r;
}
__device__ __forceinline__ void upk2(u64 v, float& lo, float& hi) {
    asm("mov.b64 {%0, %1}, %2;" : "=f"(lo), "=f"(hi) : "l"(v));
}
__device__ __forceinline__ void ffma2(u64& c, u64 a, u64 b) {
    asm("fma.rn.f32x2 %0, %1, %2, %0;" : "+l"(c) : "l"(a), "l"(b));
}
__device__ __forceinline__ unsigned sm2u(const void* p) {
    unsigned r;
    asm("{ .reg .u64 t; cvta.to.shared.u64 t, %1; cvt.u32.u64 %0, t; }"
        : "=r"(r) : "l"(p));
    return r;
}
#define CPA16(s, g) asm volatile("cp.async.cg.shared.global [%0], [%1], 16;" :: "r"(s), "l"(g))
#define CPA4(s, g)  asm volatile("cp.async.ca.shared.global [%0], [%1], 4;"  :: "r"(s), "l"(g))
#define CPCOMMIT()  asm volatile("cp.async.commit_group;" ::: "memory")
#define CPWAIT(n)   asm volatile("cp.async.wait_group %0;" :: "n"(n) : "memory")

// ---------- K0: clear ----------
__global__ void k_clear() {
    int i = threadIdx.x;
    if (i < 256) g_h256[i] = 0u;
    if (i < NW) g_valid[i] = 0ull;
    if (i == 0) { g_gcnt = 0u; g_pref = 0u; g_above2 = 0u; }
}

// ---------- prep: zero-pad ----------
__global__ void k_pad(const float* __restrict__ feat) {
    int i = blockIdx.x * 256 + threadIdx.x;
    if (i >= CCH * PADA) return;
    int ci = i / PADA, rem = i % PADA;
    int y = rem / PADW, x = rem % PADW;
    float v = 0.f;
    if (y >= 1 && y <= GH && x >= 1 && x <= GW)
        v = feat[ci * NPIX + (y - 1) * GW + (x - 1)];
    g_pad[i] = v;
}

// ---------- prep: weight transpose + dup ----------
__global__ void k_wprep(const float* __restrict__ w) {
    int i = blockIdx.x * 256 + threadIdx.x;
    if (i >= 9 * CCH * CCH) return;
    int tap = i / (CCH*CCH), r = i % (CCH*CCH);
    int ci = r >> 8, co = r & 255;
    float v = w[(size_t)co * (CCH*9) + ci * 9 + tap];
    g_wt[i] = pk2(v, v);
}

// ---------- K1: conv implicit GEMM + 4-stage cp.async pipeline ----------
__global__ __launch_bounds__(256, 2)
void k_conv(const float* __restrict__ bias) {
    __shared__ __align__(16) u64   As[4][8][128];    // 32 KB
    __shared__ __align__(16) float Bs[4][8][4][32];  // 16 KB
    int tid = threadIdx.x;
    int cog = tid >> 4;
    int pxg = tid & 15;
    int rr  = pxg >> 2;
    int cc0 = (pxg & 3) * 8;
    int gqA = (((cc0 >> 2) + 0) ^ rr) << 2;
    int gqB = (((cc0 >> 2) + 1) ^ rr) << 2;
    int pt  = blockIdx.x;
    int ty  = pt / 5, tx = pt % 5;
    int y0  = ty * 4, x0 = tx * 32;
    int co0 = blockIdx.y * 128;

    int aoff0, aoff1, asto0, asto1;
    {
        int j0 = tid * 2, j1 = (tid + 256) * 2;
        aoff0 = (j0 >> 7) * 256 + co0 + (j0 & 127);
        aoff1 = (j1 >> 7) * 256 + co0 + (j1 & 127);
        asto0 = (j0 >> 7) * 128 + (j0 & 127);
        asto1 = (j1 >> 7) * 128 + (j1 & 127);
    }
    int binv[4], bsto[4];
#pragma unroll
    for (int q = 0; q < 4; q++) {
        int f = tid + q * 256;
        int k = f >> 7, r2 = (f >> 5) & 3, cc = f & 31;
        binv[q] = k * PADA + (y0 + r2) * PADW + x0 + cc;
        bsto[q] = (k * 4 + r2) * 32 + ((((cc >> 2) ^ r2) << 2) | (cc & 3));
    }
    unsigned baseA = sm2u(&As[0][0][0]);
    unsigned baseB = sm2u(&Bs[0][0][0][0]);
    unsigned dA0 = baseA + asto0 * 8, dA1 = baseA + asto1 * 8;
    unsigned dB0 = baseB + bsto[0] * 4, dB1 = baseB + bsto[1] * 4;
    unsigned dB2 = baseB + bsto[2] * 4, dB3 = baseB + bsto[3] * 4;

    u64 acc[8][4];
#pragma unroll
    for (int u = 0; u < 8; u++)
#pragma unroll
        for (int p = 0; p < 4; p++) acc[u][p] = 0ull;

    auto issueCh = [&](int ch) {
        int buf = ch & 3;
        int tap = ch >> 5;
        int ky = (tap * 11) >> 5;
        int kx = tap - ky * 3;
        int offB = ((ch & 31) << 3) * PADA + ky * PADW + kx;
        const char* apb = (const char*)g_wt + (size_t)ch * 16384;
        unsigned oa = buf * 8192;
        unsigned ob = buf * 4096;
        CPA16(dA0 + oa, apb + (size_t)aoff0 * 8);
        CPA16(dA1 + oa, apb + (size_t)aoff1 * 8);
        const float* bp = g_pad + offB;
        CPA4(dB0 + ob, bp + binv[0]);
        CPA4(dB1 + ob, bp + binv[1]);
        CPA4(dB2 + ob, bp + binv[2]);
        CPA4(dB3 + ob, bp + binv[3]);
        CPCOMMIT();
    };

    issueCh(0);
    issueCh(1);
    issueCh(2);
    for (int ch = 0; ch < 288; ch++) {
        // wait for chunk ch's group; depth shrinks in epilogue
        if (ch < 286)       CPWAIT(2);
        else if (ch == 286) CPWAIT(1);
        else                CPWAIT(0);
        __syncthreads();
        if (ch + 3 < 288) issueCh(ch + 3);
        int buf = ch & 3;
#pragma unroll
        for (int k = 0; k < 8; k++) {
            ulonglong2 bA = *(const ulonglong2*)&Bs[buf][k][rr][gqA];
            ulonglong2 bB = *(const ulonglong2*)&Bs[buf][k][rr][gqB];
#pragma unroll
            for (int uu = 0; uu < 4; uu++) {
                ulonglong2 a = *(const ulonglong2*)&As[buf][k][cog * 8 + uu * 2];
                ffma2(acc[uu*2+0][0], bA.x, a.x);
                ffma2(acc[uu*2+0][1], bA.y, a.x);
                ffma2(acc[uu*2+0][2], bB.x, a.x);
                ffma2(acc[uu*2+0][3], bB.y, a.x);
                ffma2(acc[uu*2+1][0], bA.x, a.y);
                ffma2(acc[uu*2+1][1], bA.y, a.y);
                ffma2(acc[uu*2+1][2], bB.x, a.y);
                ffma2(acc[uu*2+1][3], bB.y, a.y);
            }
        }
        __syncthreads();
    }

#pragma unroll
    for (int u = 0; u < 8; u++) {
        int co = co0 + cog * 8 + u;
        float bb = bias[co];
        float v[8];
#pragma unroll
        for (int p = 0; p < 4; p++) upk2(acc[u][p], v[2*p], v[2*p+1]);
#pragma unroll
        for (int q = 0; q < 8; q++) v[q] = fmaxf(v[q] + bb, 0.f);
        size_t o = (size_t)co * NPIX + (y0 + rr) * GW + x0 + cc0;
        *(float4*)&g_feat[o]     = make_float4(v[0], v[1], v[2], v[3]);
        *(float4*)&g_feat[o + 4] = make_float4(v[4], v[5], v[6], v[7]);
    }
}

// ---------- K2: heads (float4 weights) + decode ----------
__global__ __launch_bounds__(128)
void k_heads(const float* __restrict__ cls_w, const float* __restrict__ cls_b,
             const float* __restrict__ bbox_w, const float* __restrict__ bbox_b) {
    __shared__ __align__(16) float ws[45][256];
    __shared__ float bs[45];
    int tid = threadIdx.x;
    for (int t = tid; t < 45*256; t += 128) {
        int j = t / 256, c = t % 256;
        ws[j][c] = (j < 9) ? cls_w[j*256 + c] : bbox_w[(j-9)*256 + c];
    }
    if (tid < 45) bs[tid] = (tid < 9) ? cls_b[tid] : bbox_b[tid - 9];
    __syncthreads();

    int pix = blockIdx.x * 128 + tid;
    float acc[45];
#pragma unroll
    for (int j = 0; j < 45; j++) acc[j] = 0.f;
    for (int c0 = 0; c0 < 256; c0 += 4) {
        float f0 = g_feat[(c0 + 0) * NPIX + pix];
        float f1 = g_feat[(c0 + 1) * NPIX + pix];
        float f2 = g_feat[(c0 + 2) * NPIX + pix];
        float f3 = g_feat[(c0 + 3) * NPIX + pix];
#pragma unroll
        for (int j = 0; j < 45; j++) {
            float4 w4 = *(const float4*)&ws[j][c0];
            float a = acc[j];
            a = fmaf(w4.x, f0, a);
            a = fmaf(w4.y, f1, a);
            a = fmaf(w4.z, f2, a);
            a = fmaf(w4.w, f3, a);
            acc[j] = a;
        }
    }
#pragma unroll
    for (int j = 0; j < 45; j++) acc[j] += bs[j];

    int y = pix / GW, x = pix % GW;
    float fx = (float)(x * STRIDE), fy = (float)(y * STRIDE);
    const float ars[3] = {0.5f, 1.0f, 2.0f};
    const float scl[3] = {128.f, 256.f, 512.f};

#pragma unroll
    for (int a = 0; a < NA; a++) {
        int ai = a / 3, si = a % 3;
        float hr = sqrtf(ars[ai]);
        float wr = __fdiv_rn(1.0f, hr);
        float wsz = __fmul_rn(wr, scl[si]);
        float hsz = __fmul_rn(hr, scl[si]);
        float bx1 = rintf(__fmul_rn(-wsz, 0.5f));
        float bx2 = rintf(__fmul_rn( wsz, 0.5f));
        float by1 = rintf(__fmul_rn(-hsz, 0.5f));
        float by2 = rintf(__fmul_rn( hsz, 0.5f));
        float ax1 = __fadd_rn(fx, bx1), ax2 = __fadd_rn(fx, bx2);
        float ay1 = __fadd_rn(fy, by1), ay2 = __fadd_rn(fy, by2);
        float aw = __fsub_rn(ax2, ax1), ah = __fsub_rn(ay2, ay1);
        float cx = __fadd_rn(ax1, __fmul_rn(0.5f, aw));
        float cy = __fadd_rn(ay1, __fmul_rn(0.5f, ah));

        float score = __fdiv_rn(1.0f, __fadd_rn(1.0f, expf(-acc[a])));

        float dx = acc[9 + a*4 + 0];
        float dy = acc[9 + a*4 + 1];
        float dw = fminf(acc[9 + a*4 + 2], DWHC);
        float dh = fminf(acc[9 + a*4 + 3], DWHC);

        float pcx = __fadd_rn(__fmul_rn(dx, aw), cx);
        float pcy = __fadd_rn(__fmul_rn(dy, ah), cy);
        float pw  = __fmul_rn(expf(dw), aw);
        float ph  = __fmul_rn(expf(dh), ah);

        float x1 = __fsub_rn(pcx, __fmul_rn(0.5f, pw));
        float x2 = __fadd_rn(pcx, __fmul_rn(0.5f, pw));
        float y1 = __fsub_rn(pcy, __fmul_rn(0.5f, ph));
        float y2 = __fadd_rn(pcy, __fmul_rn(0.5f, ph));
        x1 = fminf(fmaxf(x1, 0.f), IMG);
        x2 = fminf(fmaxf(x2, 0.f), IMG);
        y1 = fminf(fmaxf(y1, 0.f), IMG);
        y2 = fminf(fmaxf(y2, 0.f), IMG);

        int idx = pix * NA + a;
        g_boxes[idx] = make_float4(x1, y1, x2, y2);
        g_scores[idx] = score;
        unsigned b = __float_as_uint(score);
        g_keys[idx] = b ^ ((b & 0x80000000u) ? 0xFFFFFFFFu : 0x80000000u);
    }
}

// ---------- radix select: 8-bit digit passes ----------
__global__ void k_hist8(int shift, unsigned pmask) {
    __shared__ unsigned sh[256];
    int t = threadIdx.x;
    for (int i = t; i < 256; i += 1024) sh[i] = 0;
    __syncthreads();
    int i = blockIdx.x * 1024 + t;
    unsigned key = g_keys[i];
    unsigned pref = g_pref;
    bool c = ((key & pmask) == (pref & pmask));
    unsigned act = __ballot_sync(0xFFFFFFFFu, c);
    if (c) {
        unsigned bin = (key >> shift) & 255u;
        unsigned m = __match_any_sync(act, bin);
        if ((t & 31) == (unsigned)(__ffs(m) - 1))
            atomicAdd(&sh[bin], __popc(m));
    }
    __syncthreads();
    for (int b = t; b < 256; b += 1024)
        if (sh[b]) atomicAdd(&g_h256[b], sh[b]);
}

__global__ void k_scan8(int shift, int last) {
    __shared__ unsigned bins[256];
    int t = threadIdx.x;
    bins[t] = g_h256[t];
    g_h256[t] = 0;
    __syncthreads();
    if (t == 0) {
        unsigned acc = g_above2;
        for (int b = 255; b >= 0; b--) {
            unsigned h = bins[b];
            if (acc < TOPK && acc + h >= TOPK) {
                g_pref |= ((unsigned)b) << shift;
                g_above2 = acc;
                if (last) g_thr = g_pref;
                break;
            }
            acc += h;
        }
    }
}

__global__ void k_gather() {
    __shared__ unsigned wcnt[32], wbase[32], bbase;
    int i = blockIdx.x * 1024 + threadIdx.x;
    unsigned key = g_keys[i];
    bool win = key >= g_thr;
    unsigned b = __ballot_sync(0xFFFFFFFFu, win);
    unsigned lane = threadIdx.x & 31, wid = threadIdx.x >> 5;
    if (lane == 0) wcnt[wid] = __popc(b);
    __syncthreads();
    if (threadIdx.x == 0) {
        unsigned tot = 0;
        for (int w = 0; w < 32; w++) { wbase[w] = tot; tot += wcnt[w]; }
        bbase = atomicAdd(&g_gcnt, tot);
    }
    __syncthreads();
    if (win) {
        unsigned pos = bbase + wbase[wid] + __popc(b & ((1u << lane) - 1u));
        if (pos < GCAP)
            g_gath[pos] = ((u64)key << 32) | (unsigned)(~i);
    }
}

// ---------- bitonic sort in shared memory ----------
__global__ void k_sort() {
    extern __shared__ u64 s[];
    int t = threadIdx.x;
    unsigned n = g_gcnt; if (n > GCAP) n = GCAP;
    for (int i = t; i < GCAP; i += 1024)
        s[i] = (i < (int)n) ? g_gath[i] : 0ull;
    __syncthreads();
    for (int k = 2; k <= GCAP; k <<= 1) {
        for (int j = k >> 1; j > 0; j >>= 1) {
            int ls = __ffs(j) - 1;
            for (int p = t; p < GCAP/2; p += 1024) {
                int i = ((p >> ls) << (ls + 1)) | (p & (j - 1));
                int x = i + j;
                u64 a = s[i], b = s[x];
                bool desc = ((i & k) == 0);
                if ((a < b) == desc) { s[i] = b; s[x] = a; }
            }
            __syncthreads();
        }
    }
    for (int i = t; i < TOPK; i += 1024) g_gath[i] = s[i];
}

// ---------- unpack top-6000 ----------
__global__ void k_post() {
    int i = blockIdx.x * 128 + threadIdx.x;
    if (i >= TOPK) return;
    u64 kk = g_gath[i];
    unsigned idx = ~(unsigned)(kk & 0xFFFFFFFFull);
    float4 b = g_boxes[idx];
    g_tb[i] = b;
    float bw = __fsub_rn(b.z, b.x), bh = __fsub_rn(b.w, b.y);
    g_tarea[i] = __fmul_rn(bw, bh);
    g_tsc[i] = g_scores[idx];
    if (bw >= MINSZ && bh >= MINSZ)
        atomicOr(&g_valid[i >> 6], 1ull << (i & 63));
}

// ---------- NMS mask ----------
__global__ void k_mask() {
    int bi = blockIdx.y, bj = blockIdx.x;
    __shared__ float4 cb[64];
    __shared__ float  ca[64];
    int jb = bj * 64;
    int nc = min(64, TOPK - jb);
    int t = threadIdx.x;
    if (t < nc) { cb[t] = g_tb[jb + t]; ca[t] = g_tarea[jb + t]; }
    __syncthreads();
    int i = bi * 64 + t;
    if (i >= TOPK) return;
    u64 w = 0ull;
    if (bj >= bi) {
        float4 b = g_tb[i];
        float ai = g_tarea[i];
        for (int c = 0; c < nc; c++) {
            int j = jb + c;
            if (j <= i) continue;
            float4 o = cb[c];
            float xl = fmaxf(b.x, o.x), yt = fmaxf(b.y, o.y);
            float xr = fminf(b.z, o.z), yb = fminf(b.w, o.w);
            float iw = fmaxf(__fsub_rn(xr, xl), 0.f);
            float ih = fmaxf(__fsub_rn(yb, yt), 0.f);
            float inter = __fmul_rn(iw, ih);
            float iou = __fdiv_rn(inter, __fsub_rn(__fadd_rn(ai, ca[c]), inter));
            if (iou > NMS_THR) w |= 1ull << c;
        }
    }
    g_mask[(size_t)i * NW + bj] = w;
}

// ---------- NMS reduce ----------
__global__ void k_reduce() {
    extern __shared__ u64 dynsm[];
    __shared__ u64 remv[NW];
    __shared__ u64 curKept;
    int t = threadIdx.x;
    u64* buf0 = dynsm;
    u64* buf1 = dynsm + 64 * NW;
    if (t < NW) remv[t] = 0ull;
    for (int idx = t; idx < 64 * NW; idx += 256) {
        int r = idx / NW, wd = idx - r * NW;
        buf0[idx] = g_mask[(size_t)r * NW + wd];
    }
    __syncthreads();
    for (int cw = 0; cw < NW; cw++) {
        u64* cur = (cw & 1) ? buf1 : buf0;
        u64* nxt = (cw & 1) ? buf0 : buf1;
        int base = cw * 64;
        int nr = min(64, TOPK - base);
        if (t >= 96 && cw + 1 < NW) {
            int base2 = (cw + 1) * 64;
            int nr2 = min(64, TOPK - base2);
            int wd = cw + 1 + (t - 96);
            if (wd < NW) {
                const u64* src = g_mask + (size_t)base2 * NW + wd;
#pragma unroll 4
                for (int r = 0; r < nr2; r++)
                    nxt[r * NW + wd] = src[(size_t)r * NW];
            }
        }
        if (t == 0) {
            u64 span = (nr == 64) ? ~0ull : ((1ull << nr) - 1ull);
            u64 rem = remv[cw] | ~g_valid[cw];
            u64 live = ~rem & span;
            while (live) {
                int b = __ffsll(live) - 1;
                rem |= cur[b * NW + cw];
                live &= live - 1;
                live &= ~rem;
            }
            remv[cw] = rem;
            curKept = ~rem & span;
        }
        __syncthreads();
        u64 kept = curKept;
        if (t > cw && t < NW) {
            u64 a = remv[t], kk = kept;
            while (kk) {
                int b = __ffsll(kk) - 1;
                kk &= kk - 1;
                a |= cur[b * NW + t];
            }
            remv[t] = a;
        }
        __syncthreads();
    }
    if (t < NW) g_remv[t] = remv[t];
}

// ---------- emit top-300 ----------
__global__ void k_out(float* __restrict__ out) {
    __shared__ u64 keep[NW];
    __shared__ int ks[NW], ns[NW];
    __shared__ int Kc;
    int t = threadIdx.x;
    if (t < NW) {
        u64 k = ~g_remv[t];
        if (t == NW - 1) k &= (1ull << 48) - 1ull;
        keep[t] = k;
    }
    __syncthreads();
    if (t == 0) {
        int a = 0, b = 0;
        for (int w = 0; w < NW; w++) {
            ks[w] = a; ns[w] = b;
            int nb = (w == NW - 1) ? 48 : 64;
            int p = __popcll(keep[w]);
            a += p; b += nb - p;
        }
        Kc = min(a, POSTK);
    }
    __syncthreads();
    int kc = Kc;
    for (int i = t; i < TOPK; i += 128) {
        int w = i >> 6, b = i & 63;
        u64 kw = keep[w];
        u64 low = (b == 0) ? 0ull : (kw & ((1ull << b) - 1ull));
        bool isk = (kw >> b) & 1ull;
        if (isk) {
            int pos = ks[w] + __popcll(low);
            if (pos < POSTK) {
                float4 bb = g_tb[i];
                out[pos*5+0] = bb.x; out[pos*5+1] = bb.y;
                out[pos*5+2] = bb.z; out[pos*5+3] = bb.w;
                out[pos*5+4] = g_tsc[i];
            }
        } else {
            u64 nlow = (b == 0) ? 0ull : ((~kw) & ((1ull << b) - 1ull));
            int pos = kc + ns[w] + __popcll(nlow);
            if (pos < POSTK) {
                float4 bb = g_tb[i];
                out[pos*5+0] = bb.x; out[pos*5+1] = bb.y;
                out[pos*5+2] = bb.z; out[pos*5+3] = bb.w;
                out[pos*5+4] = -1.0f;
            }
        }
    }
}

extern "C" void kernel_launch(void* const* d_in, const int* in_sizes, int n_in,
                              void* d_out, int out_size) {
    const float* feat   = (const float*)d_in[0];
    const float* conv_w = (const float*)d_in[2];
    const float* conv_b = (const float*)d_in[3];
    const float* cls_w  = (const float*)d_in[4];
    const float* cls_b  = (const float*)d_in[5];
    const float* bbox_w = (const float*)d_in[6];
    const float* bbox_b = (const float*)d_in[7];
    float* out = (float*)d_out;

    cudaFuncSetAttribute(k_sort, cudaFuncAttributeMaxDynamicSharedMemorySize,
                         GCAP * sizeof(u64));
    cudaFuncSetAttribute(k_reduce, cudaFuncAttributeMaxDynamicSharedMemorySize,
                         2 * 64 * NW * sizeof(u64));

    k_clear<<<1, 256>>>();
    k_pad<<<(CCH*PADA + 255) / 256, 256>>>(feat);
    k_wprep<<<(9*CCH*CCH + 255) / 256, 256>>>(conv_w);
    k_conv<<<dim3(200, 2), 256>>>(conv_b);
    k_heads<<<200, 128>>>(cls_w, cls_b, bbox_w, bbox_b);
    k_hist8<<<225, 1024>>>(24, 0x00000000u);
    k_scan8<<<1, 256>>>(24, 0);
    k_hist8<<<225, 1024>>>(16, 0xFF000000u);
    k_scan8<<<1, 256>>>(16, 0);
    k_hist8<<<225, 1024>>>(8,  0xFFFF0000u);
    k_scan8<<<1, 256>>>(8, 0);
    k_hist8<<<225, 1024>>>(0,  0xFFFFFF00u);
    k_scan8<<<1, 256>>>(0, 1);
    k_gather<<<225, 1024>>>();
    k_sort<<<1, 1024, GCAP * sizeof(u64)>>>();
    k_post<<<47, 128>>>();
    k_mask<<<dim3(94, 94), 64>>>();
    k_reduce<<<1, 256, 2 * 64 * NW * sizeof(u64)>>>();
    k_out<<<1, 128>>>(out);
}

// round 16
// speedup vs baseline: 1.1007x; 1.0058x over previous
#include <cuda_runtime.h>
#include <math.h>

#define GH 160
#define GW 160
#define NPIX (GH*GW)
#define CCH 256
#define NA 9
#define NANCH (NPIX*NA)
#define TOPK 6000
#define NW 94
#define POSTK 300
#define GCAP 8192
#define IMG 2560.0f
#define STRIDE 16
#define DWHC ((float)4.135166556742356)
#define NMS_THR 0.7f
#define MINSZ 16.0f
#define PADW 162
#define PADA (PADW*PADW)

typedef unsigned long long u64;

// ---------- static scratch ----------
__device__ __align__(16) float  g_pad[CCH*PADA];
__device__ __align__(16) u64    g_wt[9*CCH*CCH];     // [tap][ci][co] dup (w,w)
__device__ __align__(16) float  g_feat[CCH*NPIX];
__device__ float4 g_boxes[NANCH];
__device__ float  g_scores[NANCH];
__device__ __align__(16) unsigned g_keys[NANCH];
__device__ unsigned g_h256[256];
__device__ unsigned g_pref, g_above2, g_thr, g_gcnt;
__device__ u64    g_gath[GCAP];
__device__ float4 g_tb[TOPK];
__device__ float  g_tarea[TOPK];
__device__ float  g_tsc[TOPK];
__device__ u64    g_valid[NW];
__device__ u64    g_mask[(size_t)TOPK*NW];
__device__ u64    g_remv[NW];

// ---------- helpers ----------
__device__ __forceinline__ u64 pk2(float lo, float hi) {
    u64 r; asm("mov.b64 %0, {%1, %2};" : "=l"(r) : "f"(lo), "f"(hi)); return r;
}
__device__ __forceinline__ void upk2(u64 v, float& lo, float& hi) {
    asm("mov.b64 {%0, %1}, %2;" : "=f"(lo), "=f"(hi) : "l"(v));
}
__device__ __forceinline__ void ffma2(u64& c, u64 a, u64 b) {
    asm("fma.rn.f32x2 %0, %1, %2, %0;" : "+l"(c) : "l"(a), "l"(b));
}
__device__ __forceinline__ unsigned sm2u(const void* p) {
    unsigned r;
    asm("{ .reg .u64 t; cvta.to.shared.u64 t, %1; cvt.u32.u64 %0, t; }"
        : "=r"(r) : "l"(p));
    return r;
}
#define CPA16(s, g) asm volatile("cp.async.cg.shared.global [%0], [%1], 16;" :: "r"(s), "l"(g))
#define CPA4(s, g)  asm volatile("cp.async.ca.shared.global [%0], [%1], 4;"  :: "r"(s), "l"(g))
#define CPCOMMIT()  asm volatile("cp.async.commit_group;" ::: "memory")
#define CPWAIT(n)   asm volatile("cp.async.wait_group %0;" :: "n"(n) : "memory")

// ---------- K0: clear ----------
__global__ void k_clear() {
    int i = threadIdx.x;
    if (i < 256) g_h256[i] = 0u;
    if (i < NW) g_valid[i] = 0ull;
    if (i == 0) { g_gcnt = 0u; g_pref = 0u; g_above2 = 0u; }
}

// ---------- prep: zero-pad ----------
__global__ void k_pad(const float* __restrict__ feat) {
    int i = blockIdx.x * 256 + threadIdx.x;
    if (i >= CCH * PADA) return;
    int ci = i / PADA, rem = i % PADA;
    int y = rem / PADW, x = rem % PADW;
    float v = 0.f;
    if (y >= 1 && y <= GH && x >= 1 && x <= GW)
        v = feat[ci * NPIX + (y - 1) * GW + (x - 1)];
    g_pad[i] = v;
}

// ---------- prep: weight transpose + dup ----------
__global__ void k_wprep(const float* __restrict__ w) {
    int i = blockIdx.x * 256 + threadIdx.x;
    if (i >= 9 * CCH * CCH) return;
    int tap = i / (CCH*CCH), r = i % (CCH*CCH);
    int ci = r >> 8, co = r & 255;
    float v = w[(size_t)co * (CCH*9) + ci * 9 + tap];
    g_wt[i] = pk2(v, v);
}

// ---------- K1: conv implicit GEMM + 4-stage cp.async, single barrier/chunk ----------
__global__ __launch_bounds__(256, 2)
void k_conv(const float* __restrict__ bias) {
    __shared__ __align__(16) u64   As[4][8][128];
    __shared__ __align__(16) float Bs[4][8][4][32];
    int tid = threadIdx.x;
    int cog = tid >> 4;
    int pxg = tid & 15;
    int rr  = pxg >> 2;
    int cc0 = (pxg & 3) * 8;
    int gqA = (((cc0 >> 2) + 0) ^ rr) << 2;
    int gqB = (((cc0 >> 2) + 1) ^ rr) << 2;
    int pt  = blockIdx.x;
    int ty  = pt / 5, tx = pt % 5;
    int y0  = ty * 4, x0 = tx * 32;
    int co0 = blockIdx.y * 128;

    int aoff0, aoff1, asto0, asto1;
    {
        int j0 = tid * 2, j1 = (tid + 256) * 2;
        aoff0 = (j0 >> 7) * 256 + co0 + (j0 & 127);
        aoff1 = (j1 >> 7) * 256 + co0 + (j1 & 127);
        asto0 = (j0 >> 7) * 128 + (j0 & 127);
        asto1 = (j1 >> 7) * 128 + (j1 & 127);
    }
    int binv[4], bsto[4];
#pragma unroll
    for (int q = 0; q < 4; q++) {
        int f = tid + q * 256;
        int k = f >> 7, r2 = (f >> 5) & 3, cc = f & 31;
        binv[q] = k * PADA + (y0 + r2) * PADW + x0 + cc;
        bsto[q] = (k * 4 + r2) * 32 + ((((cc >> 2) ^ r2) << 2) | (cc & 3));
    }
    unsigned baseA = sm2u(&As[0][0][0]);
    unsigned baseB = sm2u(&Bs[0][0][0][0]);
    unsigned dA0 = baseA + asto0 * 8, dA1 = baseA + asto1 * 8;
    unsigned dB0 = baseB + bsto[0] * 4, dB1 = baseB + bsto[1] * 4;
    unsigned dB2 = baseB + bsto[2] * 4, dB3 = baseB + bsto[3] * 4;

    u64 acc[8][4];
#pragma unroll
    for (int u = 0; u < 8; u++)
#pragma unroll
        for (int p = 0; p < 4; p++) acc[u][p] = 0ull;

    auto issueCh = [&](int ch) {
        int buf = ch & 3;
        int tap = ch >> 5;
        int ky = (tap * 11) >> 5;
        int kx = tap - ky * 3;
        int offB = ((ch & 31) << 3) * PADA + ky * PADW + kx;
        const char* apb = (const char*)g_wt + (size_t)ch * 16384;
        unsigned oa = buf * 8192;
        unsigned ob = buf * 4096;
        CPA16(dA0 + oa, apb + (size_t)aoff0 * 8);
        CPA16(dA1 + oa, apb + (size_t)aoff1 * 8);
        const float* bp = g_pad + offB;
        CPA4(dB0 + ob, bp + binv[0]);
        CPA4(dB1 + ob, bp + binv[1]);
        CPA4(dB2 + ob, bp + binv[2]);
        CPA4(dB3 + ob, bp + binv[3]);
        CPCOMMIT();
    };

    issueCh(0);
    issueCh(1);
    issueCh(2);
    for (int ch = 0; ch < 288; ch++) {
        if (ch < 286)       CPWAIT(2);
        else if (ch == 286) CPWAIT(1);
        else                CPWAIT(0);
        __syncthreads();                     // single barrier: publishes group ch,
                                             // and orders compute(ch-1) before issue(ch+3)
        if (ch + 3 < 288) issueCh(ch + 3);
        int buf = ch & 3;
#pragma unroll
        for (int k = 0; k < 8; k++) {
            ulonglong2 bA = *(const ulonglong2*)&Bs[buf][k][rr][gqA];
            ulonglong2 bB = *(const ulonglong2*)&Bs[buf][k][rr][gqB];
#pragma unroll
            for (int uu = 0; uu < 4; uu++) {
                ulonglong2 a = *(const ulonglong2*)&As[buf][k][cog * 8 + uu * 2];
                ffma2(acc[uu*2+0][0], bA.x, a.x);
                ffma2(acc[uu*2+0][1], bA.y, a.x);
                ffma2(acc[uu*2+0][2], bB.x, a.x);
                ffma2(acc[uu*2+0][3], bB.y, a.x);
                ffma2(acc[uu*2+1][0], bA.x, a.y);
                ffma2(acc[uu*2+1][1], bA.y, a.y);
                ffma2(acc[uu*2+1][2], bB.x, a.y);
                ffma2(acc[uu*2+1][3], bB.y, a.y);
            }
        }
    }

#pragma unroll
    for (int u = 0; u < 8; u++) {
        int co = co0 + cog * 8 + u;
        float bb = bias[co];
        float v[8];
#pragma unroll
        for (int p = 0; p < 4; p++) upk2(acc[u][p], v[2*p], v[2*p+1]);
#pragma unroll
        for (int q = 0; q < 8; q++) v[q] = fmaxf(v[q] + bb, 0.f);
        size_t o = (size_t)co * NPIX + (y0 + rr) * GW + x0 + cc0;
        *(float4*)&g_feat[o]     = make_float4(v[0], v[1], v[2], v[3]);
        *(float4*)&g_feat[o + 4] = make_float4(v[4], v[5], v[6], v[7]);
    }
}

// ---------- K2: heads + decode + keys + FUSED first radix pass ----------
__global__ __launch_bounds__(128)
void k_heads(const float* __restrict__ cls_w, const float* __restrict__ cls_b,
             const float* __restrict__ bbox_w, const float* __restrict__ bbox_b) {
    __shared__ __align__(16) float ws[45][256];
    __shared__ float bs[45];
    __shared__ unsigned hh[256];
    int tid = threadIdx.x;
    for (int t = tid; t < 45*256; t += 128) {
        int j = t / 256, c = t % 256;
        ws[j][c] = (j < 9) ? cls_w[j*256 + c] : bbox_w[(j-9)*256 + c];
    }
    if (tid < 45) bs[tid] = (tid < 9) ? cls_b[tid] : bbox_b[tid - 9];
    for (int t = tid; t < 256; t += 128) hh[t] = 0u;
    __syncthreads();

    int pix = blockIdx.x * 128 + tid;
    float acc[45];
#pragma unroll
    for (int j = 0; j < 45; j++) acc[j] = 0.f;
    for (int c0 = 0; c0 < 256; c0 += 4) {
        float f0 = g_feat[(c0 + 0) * NPIX + pix];
        float f1 = g_feat[(c0 + 1) * NPIX + pix];
        float f2 = g_feat[(c0 + 2) * NPIX + pix];
        float f3 = g_feat[(c0 + 3) * NPIX + pix];
#pragma unroll
        for (int j = 0; j < 45; j++) {
            float4 w4 = *(const float4*)&ws[j][c0];
            float a = acc[j];
            a = fmaf(w4.x, f0, a);
            a = fmaf(w4.y, f1, a);
            a = fmaf(w4.z, f2, a);
            a = fmaf(w4.w, f3, a);
            acc[j] = a;
        }
    }
#pragma unroll
    for (int j = 0; j < 45; j++) acc[j] += bs[j];

    int y = pix / GW, x = pix % GW;
    float fx = (float)(x * STRIDE), fy = (float)(y * STRIDE);
    const float ars[3] = {0.5f, 1.0f, 2.0f};
    const float scl[3] = {128.f, 256.f, 512.f};

#pragma unroll
    for (int a = 0; a < NA; a++) {
        int ai = a / 3, si = a % 3;
        float hr = sqrtf(ars[ai]);
        float wr = __fdiv_rn(1.0f, hr);
        float wsz = __fmul_rn(wr, scl[si]);
        float hsz = __fmul_rn(hr, scl[si]);
        float bx1 = rintf(__fmul_rn(-wsz, 0.5f));
        float bx2 = rintf(__fmul_rn( wsz, 0.5f));
        float by1 = rintf(__fmul_rn(-hsz, 0.5f));
        float by2 = rintf(__fmul_rn( hsz, 0.5f));
        float ax1 = __fadd_rn(fx, bx1), ax2 = __fadd_rn(fx, bx2);
        float ay1 = __fadd_rn(fy, by1), ay2 = __fadd_rn(fy, by2);
        float aw = __fsub_rn(ax2, ax1), ah = __fsub_rn(ay2, ay1);
        float cx = __fadd_rn(ax1, __fmul_rn(0.5f, aw));
        float cy = __fadd_rn(ay1, __fmul_rn(0.5f, ah));

        float score = __fdiv_rn(1.0f, __fadd_rn(1.0f, expf(-acc[a])));

        float dx = acc[9 + a*4 + 0];
        float dy = acc[9 + a*4 + 1];
        float dw = fminf(acc[9 + a*4 + 2], DWHC);
        float dh = fminf(acc[9 + a*4 + 3], DWHC);

        float pcx = __fadd_rn(__fmul_rn(dx, aw), cx);
        float pcy = __fadd_rn(__fmul_rn(dy, ah), cy);
        float pw  = __fmul_rn(expf(dw), aw);
        float ph  = __fmul_rn(expf(dh), ah);

        float x1 = __fsub_rn(pcx, __fmul_rn(0.5f, pw));
        float x2 = __fadd_rn(pcx, __fmul_rn(0.5f, pw));
        float y1 = __fsub_rn(pcy, __fmul_rn(0.5f, ph));
        float y2 = __fadd_rn(pcy, __fmul_rn(0.5f, ph));
        x1 = fminf(fmaxf(x1, 0.f), IMG);
        x2 = fminf(fmaxf(x2, 0.f), IMG);
        y1 = fminf(fmaxf(y1, 0.f), IMG);
        y2 = fminf(fmaxf(y2, 0.f), IMG);

        int idx = pix * NA + a;
        g_boxes[idx] = make_float4(x1, y1, x2, y2);
        g_scores[idx] = score;
        unsigned b = __float_as_uint(score);
        unsigned key = b ^ ((b & 0x80000000u) ? 0xFFFFFFFFu : 0x80000000u);
        g_keys[idx] = key;
        // fused radix pass 0 (top byte), warp-aggregated smem atomics
        unsigned bin = key >> 24;
        unsigned m = __match_any_sync(0xFFFFFFFFu, bin);
        if ((tid & 31) == (unsigned)(__ffs(m) - 1))
            atomicAdd(&hh[bin], __popc(m));
    }
    __syncthreads();
    for (int t = tid; t < 256; t += 128)
        if (hh[t]) atomicAdd(&g_h256[t], hh[t]);
}

// ---------- radix select: remaining 8-bit digit passes ----------
__global__ void k_hist8(int shift, unsigned pmask) {
    __shared__ unsigned sh[256];
    int t = threadIdx.x;
    for (int i = t; i < 256; i += 1024) sh[i] = 0;
    __syncthreads();
    int i = blockIdx.x * 1024 + t;
    unsigned key = g_keys[i];
    unsigned pref = g_pref;
    bool c = ((key & pmask) == (pref & pmask));
    unsigned act = __ballot_sync(0xFFFFFFFFu, c);
    if (c) {
        unsigned bin = (key >> shift) & 255u;
        unsigned m = __match_any_sync(act, bin);
        if ((t & 31) == (unsigned)(__ffs(m) - 1))
            atomicAdd(&sh[bin], __popc(m));
    }
    __syncthreads();
    for (int b = t; b < 256; b += 1024)
        if (sh[b]) atomicAdd(&g_h256[b], sh[b]);
}

__global__ void k_scan8(int shift, int last) {
    __shared__ unsigned bins[256];
    int t = threadIdx.x;
    bins[t] = g_h256[t];
    g_h256[t] = 0;
    __syncthreads();
    if (t == 0) {
        unsigned acc = g_above2;
        for (int b = 255; b >= 0; b--) {
            unsigned h = bins[b];
            if (acc < TOPK && acc + h >= TOPK) {
                g_pref |= ((unsigned)b) << shift;
                g_above2 = acc;
                if (last) g_thr = g_pref;
                break;
            }
            acc += h;
        }
    }
}

__global__ void k_gather() {
    __shared__ unsigned wcnt[32], wbase[32], bbase;
    int i = blockIdx.x * 1024 + threadIdx.x;
    unsigned key = g_keys[i];
    bool win = key >= g_thr;
    unsigned b = __ballot_sync(0xFFFFFFFFu, win);
    unsigned lane = threadIdx.x & 31, wid = threadIdx.x >> 5;
    if (lane == 0) wcnt[wid] = __popc(b);
    __syncthreads();
    if (threadIdx.x == 0) {
        unsigned tot = 0;
        for (int w = 0; w < 32; w++) { wbase[w] = tot; tot += wcnt[w]; }
        bbase = atomicAdd(&g_gcnt, tot);
    }
    __syncthreads();
    if (win) {
        unsigned pos = bbase + wbase[wid] + __popc(b & ((1u << lane) - 1u));
        if (pos < GCAP)
            g_gath[pos] = ((u64)key << 32) | (unsigned)(~i);
    }
}

// ---------- bitonic sort in shared memory ----------
__global__ void k_sort() {
    extern __shared__ u64 s[];
    int t = threadIdx.x;
    unsigned n = g_gcnt; if (n > GCAP) n = GCAP;
    for (int i = t; i < GCAP; i += 1024)
        s[i] = (i < (int)n) ? g_gath[i] : 0ull;
    __syncthreads();
    for (int k = 2; k <= GCAP; k <<= 1) {
        for (int j = k >> 1; j > 0; j >>= 1) {
            int ls = __ffs(j) - 1;
            for (int p = t; p < GCAP/2; p += 1024) {
                int i = ((p >> ls) << (ls + 1)) | (p & (j - 1));
                int x = i + j;
                u64 a = s[i], b = s[x];
                bool desc = ((i & k) == 0);
                if ((a < b) == desc) { s[i] = b; s[x] = a; }
            }
            __syncthreads();
        }
    }
    for (int i = t; i < TOPK; i += 1024) g_gath[i] = s[i];
}

// ---------- unpack top-6000 ----------
__global__ void k_post() {
    int i = blockIdx.x * 128 + threadIdx.x;
    if (i >= TOPK) return;
    u64 kk = g_gath[i];
    unsigned idx = ~(unsigned)(kk & 0xFFFFFFFFull);
    float4 b = g_boxes[idx];
    g_tb[i] = b;
    float bw = __fsub_rn(b.z, b.x), bh = __fsub_rn(b.w, b.y);
    g_tarea[i] = __fmul_rn(bw, bh);
    g_tsc[i] = g_scores[idx];
    if (bw >= MINSZ && bh >= MINSZ)
        atomicOr(&g_valid[i >> 6], 1ull << (i & 63));
}

// ---------- NMS mask ----------
__global__ void k_mask() {
    int bi = blockIdx.y, bj = blockIdx.x;
    __shared__ float4 cb[64];
    __shared__ float  ca[64];
    int jb = bj * 64;
    int nc = min(64, TOPK - jb);
    int t = threadIdx.x;
    if (t < nc) { cb[t] = g_tb[jb + t]; ca[t] = g_tarea[jb + t]; }
    __syncthreads();
    int i = bi * 64 + t;
    if (i >= TOPK) return;
    u64 w = 0ull;
    if (bj >= bi) {
        float4 b = g_tb[i];
        float ai = g_tarea[i];
        for (int c = 0; c < nc; c++) {
            int j = jb + c;
            if (j <= i) continue;
            float4 o = cb[c];
            float xl = fmaxf(b.x, o.x), yt = fmaxf(b.y, o.y);
            float xr = fminf(b.z, o.z), yb = fminf(b.w, o.w);
            float iw = fmaxf(__fsub_rn(xr, xl), 0.f);
            float ih = fmaxf(__fsub_rn(yb, yt), 0.f);
            float inter = __fmul_rn(iw, ih);
            float iou = __fdiv_rn(inter, __fsub_rn(__fadd_rn(ai, ca[c]), inter));
            if (iou > NMS_THR) w |= 1ull << c;
        }
    }
    g_mask[(size_t)i * NW + bj] = w;
}

// ---------- NMS reduce ----------
__global__ void k_reduce() {
    extern __shared__ u64 dynsm[];
    __shared__ u64 remv[NW];
    __shared__ u64 curKept;
    int t = threadIdx.x;
    u64* buf0 = dynsm;
    u64* buf1 = dynsm + 64 * NW;
    if (t < NW) remv[t] = 0ull;
    for (int idx = t; idx < 64 * NW; idx += 256) {
        int r = idx / NW, wd = idx - r * NW;
        buf0[idx] = g_mask[(size_t)r * NW + wd];
    }
    __syncthreads();
    for (int cw = 0; cw < NW; cw++) {
        u64* cur = (cw & 1) ? buf1 : buf0;
        u64* nxt = (cw & 1) ? buf0 : buf1;
        int base = cw * 64;
        int nr = min(64, TOPK - base);
        if (t >= 96 && cw + 1 < NW) {
            int base2 = (cw + 1) * 64;
            int nr2 = min(64, TOPK - base2);
            int wd = cw + 1 + (t - 96);
            if (wd < NW) {
                const u64* src = g_mask + (size_t)base2 * NW + wd;
#pragma unroll 4
                for (int r = 0; r < nr2; r++)
                    nxt[r * NW + wd] = src[(size_t)r * NW];
            }
        }
        if (t == 0) {
            u64 span = (nr == 64) ? ~0ull : ((1ull << nr) - 1ull);
            u64 rem = remv[cw] | ~g_valid[cw];
            u64 live = ~rem & span;
            while (live) {
                int b = __ffsll(live) - 1;
                rem |= cur[b * NW + cw];
                live &= live - 1;
                live &= ~rem;
            }
            remv[cw] = rem;
            curKept = ~rem & span;
        }
        __syncthreads();
        u64 kept = curKept;
        if (t > cw && t < NW) {
            u64 a = remv[t], kk = kept;
            while (kk) {
                int b = __ffsll(kk) - 1;
                kk &= kk - 1;
                a |= cur[b * NW + t];
            }
            remv[t] = a;
        }
        __syncthreads();
    }
    if (t < NW) g_remv[t] = remv[t];
}

// ---------- emit top-300 ----------
__global__ void k_out(float* __restrict__ out) {
    __shared__ u64 keep[NW];
    __shared__ int ks[NW], ns[NW];
    __shared__ int Kc;
    int t = threadIdx.x;
    if (t < NW) {
        u64 k = ~g_remv[t];
        if (t == NW - 1) k &= (1ull << 48) - 1ull;
        keep[t] = k;
    }
    __syncthreads();
    if (t == 0) {
        int a = 0, b = 0;
        for (int w = 0; w < NW; w++) {
            ks[w] = a; ns[w] = b;
            int nb = (w == NW - 1) ? 48 : 64;
            int p = __popcll(keep[w]);
            a += p; b += nb - p;
        }
        Kc = min(a, POSTK);
    }
    __syncthreads();
    int kc = Kc;
    for (int i = t; i < TOPK; i += 128) {
        int w = i >> 6, b = i & 63;
        u64 kw = keep[w];
        u64 low = (b == 0) ? 0ull : (kw & ((1ull << b) - 1ull));
        bool isk = (kw >> b) & 1ull;
        if (isk) {
            int pos = ks[w] + __popcll(low);
            if (pos < POSTK) {
                float4 bb = g_tb[i];
                out[pos*5+0] = bb.x; out[pos*5+1] = bb.y;
                out[pos*5+2] = bb.z; out[pos*5+3] = bb.w;
                out[pos*5+4] = g_tsc[i];
            }
        } else {
            u64 nlow = (b == 0) ? 0ull : ((~kw) & ((1ull << b) - 1ull));
            int pos = kc + ns[w] + __popcll(nlow);
            if (pos < POSTK) {
                float4 bb = g_tb[i];
                out[pos*5+0] = bb.x; out[pos*5+1] = bb.y;
                out[pos*5+2] = bb.z; out[pos*5+3] = bb.w;
                out[pos*5+4] = -1.0f;
            }
        }
    }
}

extern "C" void kernel_launch(void* const* d_in, const int* in_sizes, int n_in,
                              void* d_out, int out_size) {
    const float* feat   = (const float*)d_in[0];
    const float* conv_w = (const float*)d_in[2];
    const float* conv_b = (const float*)d_in[3];
    const float* cls_w  = (const float*)d_in[4];
    const float* cls_b  = (const float*)d_in[5];
    const float* bbox_w = (const float*)d_in[6];
    const float* bbox_b = (const float*)d_in[7];
    float* out = (float*)d_out;

    cudaFuncSetAttribute(k_sort, cudaFuncAttributeMaxDynamicSharedMemorySize,
                         GCAP * sizeof(u64));
    cudaFuncSetAttribute(k_reduce, cudaFuncAttributeMaxDynamicSharedMemorySize,
                         2 * 64 * NW * sizeof(u64));

    k_clear<<<1, 256>>>();
    k_pad<<<(CCH*PADA + 255) / 256, 256>>>(feat);
    k_wprep<<<(9*CCH*CCH + 255) / 256, 256>>>(conv_w);
    k_conv<<<dim3(200, 2), 256>>>(conv_b);
    k_heads<<<200, 128>>>(cls_w, cls_b, bbox_w, bbox_b);   // includes radix pass 0
    k_scan8<<<1, 256>>>(24, 0);
    k_hist8<<<225, 1024>>>(16, 0xFF000000u);
    k_scan8<<<1, 256>>>(16, 0);
    k_hist8<<<225, 1024>>>(8,  0xFFFF0000u);
    k_scan8<<<1, 256>>>(8, 0);
    k_hist8<<<225, 1024>>>(0,  0xFFFFFF00u);
    k_scan8<<<1, 256>>>(0, 1);
    k_gather<<<225, 1024>>>();
    k_sort<<<1, 1024, GCAP * sizeof(u64)>>>();
    k_post<<<47, 128>>>();
    k_mask<<<dim3(94, 94), 64>>>();
    k_reduce<<<1, 256, 2 * 64 * NW * sizeof(u64)>>>();
    k_out<<<1, 128>>>(out);
}

// round 17
// speedup vs baseline: 1.1049x; 1.0038x over previous
#include <cuda_runtime.h>
#include <math.h>

#define GH 160
#define GW 160
#define NPIX (GH*GW)
#define CCH 256
#define NA 9
#define NANCH (NPIX*NA)
#define NV4 (NANCH/4)
#define TOPK 6000
#define NW 94
#define POSTK 300
#define GCAP 8192
#define IMG 2560.0f
#define STRIDE 16
#define DWHC ((float)4.135166556742356)
#define NMS_THR 0.7f
#define MINSZ 16.0f
#define PADW 162
#define PADA (PADW*PADW)

typedef unsigned long long u64;

// ---------- static scratch ----------
__device__ __align__(16) float  g_pad[CCH*PADA];
__device__ __align__(16) u64    g_wt[9*CCH*CCH];     // [tap][ci][co] dup (w,w)
__device__ __align__(16) float  g_feat[CCH*NPIX];
__device__ float4 g_boxes[NANCH];
__device__ float  g_scores[NANCH];
__device__ __align__(16) unsigned g_keys[NANCH];
__device__ unsigned g_h256[256];
__device__ unsigned g_pref, g_above2, g_thr, g_gcnt;
__device__ u64    g_gath[GCAP];
__device__ float4 g_tb[TOPK];
__device__ float  g_tarea[TOPK];
__device__ float  g_tsc[TOPK];
__device__ u64    g_valid[NW];
__device__ u64    g_mask[(size_t)TOPK*NW];
__device__ u64    g_remv[NW];

// ---------- helpers ----------
__device__ __forceinline__ u64 pk2(float lo, float hi) {
    u64 r; asm("mov.b64 %0, {%1, %2};" : "=l"(r) : "f"(lo), "f"(hi)); return r;
}
__device__ __forceinline__ void upk2(u64 v, float& lo, float& hi) {
    asm("mov.b64 {%0, %1}, %2;" : "=f"(lo), "=f"(hi) : "l"(v));
}
__device__ __forceinline__ void ffma2(u64& c, u64 a, u64 b) {
    asm("fma.rn.f32x2 %0, %1, %2, %0;" : "+l"(c) : "l"(a), "l"(b));
}
__device__ __forceinline__ unsigned sm2u(const void* p) {
    unsigned r;
    asm("{ .reg .u64 t; cvta.to.shared.u64 t, %1; cvt.u32.u64 %0, t; }"
        : "=r"(r) : "l"(p));
    return r;
}
#define CPA16(s, g) asm volatile("cp.async.cg.shared.global [%0], [%1], 16;" :: "r"(s), "l"(g))
#define CPA4(s, g)  asm volatile("cp.async.ca.shared.global [%0], [%1], 4;"  :: "r"(s), "l"(g))
#define CPCOMMIT()  asm volatile("cp.async.commit_group;" ::: "memory")
#define CPWAIT(n)   asm volatile("cp.async.wait_group %0;" :: "n"(n) : "memory")

// ---------- K0: clear ----------
__global__ void k_clear() {
    int i = threadIdx.x;
    if (i < 256) g_h256[i] = 0u;
    if (i < NW) g_valid[i] = 0ull;
    if (i == 0) { g_gcnt = 0u; g_pref = 0u; g_above2 = 0u; }
}

// ---------- prep: zero-pad (4 blocks/channel, looped) ----------
__global__ __launch_bounds__(256)
void k_pad(const float* __restrict__ feat) {
    int b = blockIdx.x;
    int ci = b >> 2, grp = b & 3;
    int y0 = grp * 41;
    int ny = min(41, PADW - y0);
    const float* src = feat + (size_t)ci * NPIX;
    float* dst = g_pad + (size_t)ci * PADA + (size_t)y0 * PADW;
    int tot = ny * PADW;
    for (int idx = threadIdx.x; idx < tot; idx += 256) {
        int y = y0 + idx / PADW, x = idx % PADW;
        float v = 0.f;
        if (y >= 1 && y <= GH && x >= 1 && x <= GW)
            v = src[(y - 1) * GW + (x - 1)];
        dst[idx] = v;
    }
}

// ---------- prep: weight transpose + dup ----------
__global__ void k_wprep(const float* __restrict__ w) {
    int i = blockIdx.x * 256 + threadIdx.x;
    if (i >= 9 * CCH * CCH) return;
    int tap = i / (CCH*CCH), r = i % (CCH*CCH);
    int ci = r >> 8, co = r & 255;
    float v = w[(size_t)co * (CCH*9) + ci * 9 + tap];
    g_wt[i] = pk2(v, v);
}

// ---------- K1: conv implicit GEMM + 4-stage cp.async (measured 768us) ----------
__global__ __launch_bounds__(256, 2)
void k_conv(const float* __restrict__ bias) {
    __shared__ __align__(16) u64   As[4][8][128];
    __shared__ __align__(16) float Bs[4][8][4][32];
    int tid = threadIdx.x;
    int cog = tid >> 4;
    int pxg = tid & 15;
    int rr  = pxg >> 2;
    int cc0 = (pxg & 3) * 8;
    int gqA = (((cc0 >> 2) + 0) ^ rr) << 2;
    int gqB = (((cc0 >> 2) + 1) ^ rr) << 2;
    int pt  = blockIdx.x;
    int ty  = pt / 5, tx = pt % 5;
    int y0  = ty * 4, x0 = tx * 32;
    int co0 = blockIdx.y * 128;

    int aoff0, aoff1, asto0, asto1;
    {
        int j0 = tid * 2, j1 = (tid + 256) * 2;
        aoff0 = (j0 >> 7) * 256 + co0 + (j0 & 127);
        aoff1 = (j1 >> 7) * 256 + co0 + (j1 & 127);
        asto0 = (j0 >> 7) * 128 + (j0 & 127);
        asto1 = (j1 >> 7) * 128 + (j1 & 127);
    }
    int binv[4], bsto[4];
#pragma unroll
    for (int q = 0; q < 4; q++) {
        int f = tid + q * 256;
        int k = f >> 7, r2 = (f >> 5) & 3, cc = f & 31;
        binv[q] = k * PADA + (y0 + r2) * PADW + x0 + cc;
        bsto[q] = (k * 4 + r2) * 32 + ((((cc >> 2) ^ r2) << 2) | (cc & 3));
    }
    unsigned baseA = sm2u(&As[0][0][0]);
    unsigned baseB = sm2u(&Bs[0][0][0][0]);
    unsigned dA0 = baseA + asto0 * 8, dA1 = baseA + asto1 * 8;
    unsigned dB0 = baseB + bsto[0] * 4, dB1 = baseB + bsto[1] * 4;
    unsigned dB2 = baseB + bsto[2] * 4, dB3 = baseB + bsto[3] * 4;

    u64 acc[8][4];
#pragma unroll
    for (int u = 0; u < 8; u++)
#pragma unroll
        for (int p = 0; p < 4; p++) acc[u][p] = 0ull;

    auto issueCh = [&](int ch) {
        int buf = ch & 3;
        int tap = ch >> 5;
        int ky = (tap * 11) >> 5;
        int kx = tap - ky * 3;
        int offB = ((ch & 31) << 3) * PADA + ky * PADW + kx;
        const char* apb = (const char*)g_wt + (size_t)ch * 16384;
        unsigned oa = buf * 8192;
        unsigned ob = buf * 4096;
        CPA16(dA0 + oa, apb + (size_t)aoff0 * 8);
        CPA16(dA1 + oa, apb + (size_t)aoff1 * 8);
        const float* bp = g_pad + offB;
        CPA4(dB0 + ob, bp + binv[0]);
        CPA4(dB1 + ob, bp + binv[1]);
        CPA4(dB2 + ob, bp + binv[2]);
        CPA4(dB3 + ob, bp + binv[3]);
        CPCOMMIT();
    };

    issueCh(0);
    issueCh(1);
    issueCh(2);
    for (int ch = 0; ch < 288; ch++) {
        if (ch < 286)       CPWAIT(2);
        else if (ch == 286) CPWAIT(1);
        else                CPWAIT(0);
        __syncthreads();
        if (ch + 3 < 288) issueCh(ch + 3);
        int buf = ch & 3;
#pragma unroll
        for (int k = 0; k < 8; k++) {
            ulonglong2 bA = *(const ulonglong2*)&Bs[buf][k][rr][gqA];
            ulonglong2 bB = *(const ulonglong2*)&Bs[buf][k][rr][gqB];
#pragma unroll
            for (int uu = 0; uu < 4; uu++) {
                ulonglong2 a = *(const ulonglong2*)&As[buf][k][cog * 8 + uu * 2];
                ffma2(acc[uu*2+0][0], bA.x, a.x);
                ffma2(acc[uu*2+0][1], bA.y, a.x);
                ffma2(acc[uu*2+0][2], bB.x, a.x);
                ffma2(acc[uu*2+0][3], bB.y, a.x);
                ffma2(acc[uu*2+1][0], bA.x, a.y);
                ffma2(acc[uu*2+1][1], bA.y, a.y);
                ffma2(acc[uu*2+1][2], bB.x, a.y);
                ffma2(acc[uu*2+1][3], bB.y, a.y);
            }
        }
    }

#pragma unroll
    for (int u = 0; u < 8; u++) {
        int co = co0 + cog * 8 + u;
        float bb = bias[co];
        float v[8];
#pragma unroll
        for (int p = 0; p < 4; p++) upk2(acc[u][p], v[2*p], v[2*p+1]);
#pragma unroll
        for (int q = 0; q < 8; q++) v[q] = fmaxf(v[q] + bb, 0.f);
        size_t o = (size_t)co * NPIX + (y0 + rr) * GW + x0 + cc0;
        *(float4*)&g_feat[o]     = make_float4(v[0], v[1], v[2], v[3]);
        *(float4*)&g_feat[o + 4] = make_float4(v[4], v[5], v[6], v[7]);
    }
}

// ---------- K2: heads + decode + keys + fused radix pass 0 ----------
__global__ __launch_bounds__(128)
void k_heads(const float* __restrict__ cls_w, const float* __restrict__ cls_b,
             const float* __restrict__ bbox_w, const float* __restrict__ bbox_b) {
    __shared__ __align__(16) float ws[45][256];
    __shared__ float bs[45];
    __shared__ unsigned hh[256];
    int tid = threadIdx.x;
    for (int t = tid; t < 45*256; t += 128) {
        int j = t / 256, c = t % 256;
        ws[j][c] = (j < 9) ? cls_w[j*256 + c] : bbox_w[(j-9)*256 + c];
    }
    if (tid < 45) bs[tid] = (tid < 9) ? cls_b[tid] : bbox_b[tid - 9];
    for (int t = tid; t < 256; t += 128) hh[t] = 0u;
    __syncthreads();

    int pix = blockIdx.x * 128 + tid;
    float acc[45];
#pragma unroll
    for (int j = 0; j < 45; j++) acc[j] = 0.f;
    for (int c0 = 0; c0 < 256; c0 += 4) {
        float f0 = g_feat[(c0 + 0) * NPIX + pix];
        float f1 = g_feat[(c0 + 1) * NPIX + pix];
        float f2 = g_feat[(c0 + 2) * NPIX + pix];
        float f3 = g_feat[(c0 + 3) * NPIX + pix];
#pragma unroll
        for (int j = 0; j < 45; j++) {
            float4 w4 = *(const float4*)&ws[j][c0];
            float a = acc[j];
            a = fmaf(w4.x, f0, a);
            a = fmaf(w4.y, f1, a);
            a = fmaf(w4.z, f2, a);
            a = fmaf(w4.w, f3, a);
            acc[j] = a;
        }
    }
#pragma unroll
    for (int j = 0; j < 45; j++) acc[j] += bs[j];

    int y = pix / GW, x = pix % GW;
    float fx = (float)(x * STRIDE), fy = (float)(y * STRIDE);
    const float ars[3] = {0.5f, 1.0f, 2.0f};
    const float scl[3] = {128.f, 256.f, 512.f};

#pragma unroll
    for (int a = 0; a < NA; a++) {
        int ai = a / 3, si = a % 3;
        float hr = sqrtf(ars[ai]);
        float wr = __fdiv_rn(1.0f, hr);
        float wsz = __fmul_rn(wr, scl[si]);
        float hsz = __fmul_rn(hr, scl[si]);
        float bx1 = rintf(__fmul_rn(-wsz, 0.5f));
        float bx2 = rintf(__fmul_rn( wsz, 0.5f));
        float by1 = rintf(__fmul_rn(-hsz, 0.5f));
        float by2 = rintf(__fmul_rn( hsz, 0.5f));
        float ax1 = __fadd_rn(fx, bx1), ax2 = __fadd_rn(fx, bx2);
        float ay1 = __fadd_rn(fy, by1), ay2 = __fadd_rn(fy, by2);
        float aw = __fsub_rn(ax2, ax1), ah = __fsub_rn(ay2, ay1);
        float cx = __fadd_rn(ax1, __fmul_rn(0.5f, aw));
        float cy = __fadd_rn(ay1, __fmul_rn(0.5f, ah));

        float score = __fdiv_rn(1.0f, __fadd_rn(1.0f, expf(-acc[a])));

        float dx = acc[9 + a*4 + 0];
        float dy = acc[9 + a*4 + 1];
        float dw = fminf(acc[9 + a*4 + 2], DWHC);
        float dh = fminf(acc[9 + a*4 + 3], DWHC);

        float pcx = __fadd_rn(__fmul_rn(dx, aw), cx);
        float pcy = __fadd_rn(__fmul_rn(dy, ah), cy);
        float pw  = __fmul_rn(expf(dw), aw);
        float ph  = __fmul_rn(expf(dh), ah);

        float x1 = __fsub_rn(pcx, __fmul_rn(0.5f, pw));
        float x2 = __fadd_rn(pcx, __fmul_rn(0.5f, pw));
        float y1 = __fsub_rn(pcy, __fmul_rn(0.5f, ph));
        float y2 = __fadd_rn(pcy, __fmul_rn(0.5f, ph));
        x1 = fminf(fmaxf(x1, 0.f), IMG);
        x2 = fminf(fmaxf(x2, 0.f), IMG);
        y1 = fminf(fmaxf(y1, 0.f), IMG);
        y2 = fminf(fmaxf(y2, 0.f), IMG);

        int idx = pix * NA + a;
        g_boxes[idx] = make_float4(x1, y1, x2, y2);
        g_scores[idx] = score;
        unsigned b = __float_as_uint(score);
        unsigned key = b ^ ((b & 0x80000000u) ? 0xFFFFFFFFu : 0x80000000u);
        g_keys[idx] = key;
        unsigned bin = key >> 24;
        unsigned m = __match_any_sync(0xFFFFFFFFu, bin);
        if ((tid & 31) == (unsigned)(__ffs(m) - 1))
            atomicAdd(&hh[bin], __popc(m));
    }
    __syncthreads();
    for (int t = tid; t < 256; t += 128)
        if (hh[t]) atomicAdd(&g_h256[t], hh[t]);
}

// ---------- radix select: vectorized 8-bit digit passes ----------
__global__ __launch_bounds__(1024)
void k_hist8(int shift, unsigned pmask) {
    __shared__ unsigned sh[256];
    int t = threadIdx.x;
    if (t < 256) sh[t] = 0;
    __syncthreads();
    int i = blockIdx.x * 1024 + t;
    bool inb = i < NV4;
    uint4 kv = inb ? ((const uint4*)g_keys)[i] : make_uint4(0u,0u,0u,0u);
    unsigned pref = g_pref;
    unsigned ka[4] = {kv.x, kv.y, kv.z, kv.w};
#pragma unroll
    for (int q = 0; q < 4; q++) {
        unsigned key = ka[q];
        bool c = inb && ((key & pmask) == (pref & pmask));
        unsigned act = __ballot_sync(0xFFFFFFFFu, c);
        if (c) {
            unsigned bin = (key >> shift) & 255u;
            unsigned m = __match_any_sync(act, bin);
            if ((t & 31) == (unsigned)(__ffs(m) - 1))
                atomicAdd(&sh[bin], __popc(m));
        }
    }
    __syncthreads();
    if (t < 256 && sh[t]) atomicAdd(&g_h256[t], sh[t]);
}

__global__ void k_scan8(int shift, int last) {
    __shared__ unsigned bins[256];
    int t = threadIdx.x;
    bins[t] = g_h256[t];
    g_h256[t] = 0;
    __syncthreads();
    if (t == 0) {
        unsigned acc = g_above2;
        for (int b = 255; b >= 0; b--) {
            unsigned h = bins[b];
            if (acc < TOPK && acc + h >= TOPK) {
                g_pref |= ((unsigned)b) << shift;
                g_above2 = acc;
                if (last) g_thr = g_pref;
                break;
            }
            acc += h;
        }
    }
}

__global__ __launch_bounds__(1024)
void k_gather() {
    __shared__ unsigned wcnt[32], wbase[32], bbase;
    int t = threadIdx.x;
    unsigned lane = t & 31, wid = t >> 5;
    int i = blockIdx.x * 1024 + t;
    bool inb = i < NV4;
    uint4 kv = inb ? ((const uint4*)g_keys)[i] : make_uint4(0u,0u,0u,0u);
    unsigned thr = g_thr;
    unsigned ka[4] = {kv.x, kv.y, kv.z, kv.w};
    unsigned m[4];
    unsigned cnt = 0;
#pragma unroll
    for (int q = 0; q < 4; q++) {
        bool win = inb && (ka[q] >= thr);
        m[q] = __ballot_sync(0xFFFFFFFFu, win);
        cnt += __popc(m[q]);
    }
    if (lane == 0) wcnt[wid] = cnt;
    __syncthreads();
    if (t == 0) {
        unsigned tot = 0;
        for (int w = 0; w < 32; w++) { wbase[w] = tot; tot += wcnt[w]; }
        bbase = atomicAdd(&g_gcnt, tot);
    }
    __syncthreads();
    unsigned run = bbase + wbase[wid];
#pragma unroll
    for (int q = 0; q < 4; q++) {
        bool win = inb && (ka[q] >= thr);
        if (win) {
            unsigned pos = run + __popc(m[q] & ((1u << lane) - 1u));
            if (pos < GCAP) {
                unsigned idx = (unsigned)(i * 4 + q);
                g_gath[pos] = ((u64)ka[q] << 32) | (unsigned)(~idx);
            }
        }
        run += __popc(m[q]);
    }
}

// ---------- bitonic sort in shared memory ----------
__global__ void k_sort() {
    extern __shared__ u64 s[];
    int t = threadIdx.x;
    unsigned n = g_gcnt; if (n > GCAP) n = GCAP;
    for (int i = t; i < GCAP; i += 1024)
        s[i] = (i < (int)n) ? g_gath[i] : 0ull;
    __syncthreads();
    for (int k = 2; k <= GCAP; k <<= 1) {
        for (int j = k >> 1; j > 0; j >>= 1) {
            int ls = __ffs(j) - 1;
            for (int p = t; p < GCAP/2; p += 1024) {
                int i = ((p >> ls) << (ls + 1)) | (p & (j - 1));
                int x = i + j;
                u64 a = s[i], b = s[x];
                bool desc = ((i & k) == 0);
                if ((a < b) == desc) { s[i] = b; s[x] = a; }
            }
            __syncthreads();
        }
    }
    for (int i = t; i < TOPK; i += 1024) g_gath[i] = s[i];
}

// ---------- unpack top-6000 ----------
__global__ void k_post() {
    int i = blockIdx.x * 128 + threadIdx.x;
    if (i >= TOPK) return;
    u64 kk = g_gath[i];
    unsigned idx = ~(unsigned)(kk & 0xFFFFFFFFull);
    float4 b = g_boxes[idx];
    g_tb[i] = b;
    float bw = __fsub_rn(b.z, b.x), bh = __fsub_rn(b.w, b.y);
    g_tarea[i] = __fmul_rn(bw, bh);
    g_tsc[i] = g_scores[idx];
    if (bw >= MINSZ && bh >= MINSZ)
        atomicOr(&g_valid[i >> 6], 1ull << (i & 63));
}

// ---------- NMS mask ----------
__global__ void k_mask() {
    int bi = blockIdx.y, bj = blockIdx.x;
    __shared__ float4 cb[64];
    __shared__ float  ca[64];
    int jb = bj * 64;
    int nc = min(64, TOPK - jb);
    int t = threadIdx.x;
    if (t < nc) { cb[t] = g_tb[jb + t]; ca[t] = g_tarea[jb + t]; }
    __syncthreads();
    int i = bi * 64 + t;
    if (i >= TOPK) return;
    u64 w = 0ull;
    if (bj >= bi) {
        float4 b = g_tb[i];
        float ai = g_tarea[i];
        for (int c = 0; c < nc; c++) {
            int j = jb + c;
            if (j <= i) continue;
            float4 o = cb[c];
            float xl = fmaxf(b.x, o.x), yt = fmaxf(b.y, o.y);
            float xr = fminf(b.z, o.z), yb = fminf(b.w, o.w);
            float iw = fmaxf(__fsub_rn(xr, xl), 0.f);
            float ih = fmaxf(__fsub_rn(yb, yt), 0.f);
            float inter = __fmul_rn(iw, ih);
            float iou = __fdiv_rn(inter, __fsub_rn(__fadd_rn(ai, ca[c]), inter));
            if (iou > NMS_THR) w |= 1ull << c;
        }
    }
    g_mask[(size_t)i * NW + bj] = w;
}

// ---------- NMS reduce ----------
__global__ void k_reduce() {
    extern __shared__ u64 dynsm[];
    __shared__ u64 remv[NW];
    __shared__ u64 curKept;
    int t = threadIdx.x;
    u64* buf0 = dynsm;
    u64* buf1 = dynsm + 64 * NW;
    if (t < NW) remv[t] = 0ull;
    for (int idx = t; idx < 64 * NW; idx += 256) {
        int r = idx / NW, wd = idx - r * NW;
        buf0[idx] = g_mask[(size_t)r * NW + wd];
    }
    __syncthreads();
    for (int cw = 0; cw < NW; cw++) {
        u64* cur = (cw & 1) ? buf1 : buf0;
        u64* nxt = (cw & 1) ? buf0 : buf1;
        int base = cw * 64;
        int nr = min(64, TOPK - base);
        if (t >= 96 && cw + 1 < NW) {
            int base2 = (cw + 1) * 64;
            int nr2 = min(64, TOPK - base2);
            int wd = cw + 1 + (t - 96);
            if (wd < NW) {
                const u64* src = g_mask + (size_t)base2 * NW + wd;
#pragma unroll 4
                for (int r = 0; r < nr2; r++)
                    nxt[r * NW + wd] = src[(size_t)r * NW];
            }
        }
        if (t == 0) {
            u64 span = (nr == 64) ? ~0ull : ((1ull << nr) - 1ull);
            u64 rem = remv[cw] | ~g_valid[cw];
            u64 live = ~rem & span;
            while (live) {
                int b = __ffsll(live) - 1;
                rem |= cur[b * NW + cw];
                live &= live - 1;
                live &= ~rem;
            }
            remv[cw] = rem;
            curKept = ~rem & span;
        }
        __syncthreads();
        u64 kept = curKept;
        if (t > cw && t < NW) {
            u64 a = remv[t], kk = kept;
            while (kk) {
                int b = __ffsll(kk) - 1;
                kk &= kk - 1;
                a |= cur[b * NW + t];
            }
            remv[t] = a;
        }
        __syncthreads();
    }
    if (t < NW) g_remv[t] = remv[t];
}

// ---------- emit top-300 ----------
__global__ void k_out(float* __restrict__ out) {
    __shared__ u64 keep[NW];
    __shared__ int ks[NW], ns[NW];
    __shared__ int Kc;
    int t = threadIdx.x;
    if (t < NW) {
        u64 k = ~g_remv[t];
        if (t == NW - 1) k &= (1ull << 48) - 1ull;
        keep[t] = k;
    }
    __syncthreads();
    if (t == 0) {
        int a = 0, b = 0;
        for (int w = 0; w < NW; w++) {
            ks[w] = a; ns[w] = b;
            int nb = (w == NW - 1) ? 48 : 64;
            int p = __popcll(keep[w]);
            a += p; b += nb - p;
        }
        Kc = min(a, POSTK);
    }
    __syncthreads();
    int kc = Kc;
    for (int i = t; i < TOPK; i += 128) {
        int w = i >> 6, b = i & 63;
        u64 kw = keep[w];
        u64 low = (b == 0) ? 0ull : (kw & ((1ull << b) - 1ull));
        bool isk = (kw >> b) & 1ull;
        if (isk) {
            int pos = ks[w] + __popcll(low);
            if (pos < POSTK) {
                float4 bb = g_tb[i];
                out[pos*5+0] = bb.x; out[pos*5+1] = bb.y;
                out[pos*5+2] = bb.z; out[pos*5+3] = bb.w;
                out[pos*5+4] = g_tsc[i];
            }
        } else {
            u64 nlow = (b == 0) ? 0ull : ((~kw) & ((1ull << b) - 1ull));
            int pos = kc + ns[w] + __popcll(nlow);
            if (pos < POSTK) {
                float4 bb = g_tb[i];
                out[pos*5+0] = bb.x; out[pos*5+1] = bb.y;
                out[pos*5+2] = bb.z; out[pos*5+3] = bb.w;
                out[pos*5+4] = -1.0f;
            }
        }
    }
}

extern "C" void kernel_launch(void* const* d_in, const int* in_sizes, int n_in,
                              void* d_out, int out_size) {
    const float* feat   = (const float*)d_in[0];
    const float* conv_w = (const float*)d_in[2];
    const float* conv_b = (const float*)d_in[3];
    const float* cls_w  = (const float*)d_in[4];
    const float* cls_b  = (const float*)d_in[5];
    const float* bbox_w = (const float*)d_in[6];
    const float* bbox_b = (const float*)d_in[7];
    float* out = (float*)d_out;

    cudaFuncSetAttribute(k_sort, cudaFuncAttributeMaxDynamicSharedMemorySize,
                         GCAP * sizeof(u64));
    cudaFuncSetAttribute(k_reduce, cudaFuncAttributeMaxDynamicSharedMemorySize,
                         2 * 64 * NW * sizeof(u64));

    k_clear<<<1, 256>>>();
    k_pad<<<1024, 256>>>(feat);
    k_wprep<<<(9*CCH*CCH + 255) / 256, 256>>>(conv_w);
    k_conv<<<dim3(200, 2), 256>>>(conv_b);
    k_heads<<<200, 128>>>(cls_w, cls_b, bbox_w, bbox_b);   // includes radix pass 0
    k_scan8<<<1, 256>>>(24, 0);
    k_hist8<<<57, 1024>>>(16, 0xFF000000u);
    k_scan8<<<1, 256>>>(16, 0);
    k_hist8<<<57, 1024>>>(8,  0xFFFF0000u);
    k_scan8<<<1, 256>>>(8, 0);
    k_hist8<<<57, 1024>>>(0,  0xFFFFFF00u);
    k_scan8<<<1, 256>>>(0, 1);
    k_gather<<<57, 1024>>>();
    k_sort<<<1, 1024, GCAP * sizeof(u64)>>>();
    k_post<<<47, 128>>>();
    k_mask<<<dim3(94, 94), 64>>>();
    k_reduce<<<1, 256, 2 * 64 * NW * sizeof(u64)>>>();
    k_out<<<1, 128>>>(out);
}